// round 10
// baseline (speedup 1.0000x reference)
#include <cuda_runtime.h>
#include <cuda_bf16.h>
#include <cuda_fp16.h>
#include <math.h>
#include <stdint.h>

#define BB   2
#define SS   2048
#define DD   768
#define HH   12
#define DKK  64

#define XN 3145728   // 4096*768
#define WN 589824    // 768*768
#define HN 3145728   // BB*HH*SS*DKK
#define CN 3145728   // BB*SS*DD

// fp16 scratch (allocation-free)
__device__ __align__(128) __half g_xh[3 * XN];   // activations hi
__device__ __align__(128) __half g_xl[3 * XN];   // activations lo residual
__device__ __align__(128) __half g_wh[4 * WN];   // weights single fp16
__device__ __align__(128) __half g_qh[HN];       // q (pre-scaled by 0.125*log2e)
__device__ __align__(128) __half g_kh[HN];
__device__ __align__(128) __half g_vh[HN];
__device__ __align__(128) __half g_ch[CN];       // ctx hi
__device__ __align__(128) __half g_cl[CN];       // ctx lo residual

// ------------------------------ helpers -------------------------------------
__device__ __forceinline__ uint32_t smem_u32(const void* p) {
    return (uint32_t)__cvta_generic_to_shared(p);
}
__device__ __forceinline__ void mma16816h(float* c, const uint32_t* a,
                                          uint32_t b0, uint32_t b1) {
    asm volatile(
        "mma.sync.aligned.m16n8k16.row.col.f32.f16.f16.f32 "
        "{%0,%1,%2,%3}, {%4,%5,%6,%7}, {%8,%9}, {%0,%1,%2,%3};"
        : "+f"(c[0]), "+f"(c[1]), "+f"(c[2]), "+f"(c[3])
        : "r"(a[0]), "r"(a[1]), "r"(a[2]), "r"(a[3]), "r"(b0), "r"(b1));
}
__device__ __forceinline__ void ldmat4(uint32_t* r, uint32_t addr) {
    asm volatile(
        "ldmatrix.sync.aligned.m8n8.x4.shared.b16 {%0,%1,%2,%3}, [%4];"
        : "=r"(r[0]), "=r"(r[1]), "=r"(r[2]), "=r"(r[3]) : "r"(addr));
}
__device__ __forceinline__ void ldmat4t(uint32_t* r, uint32_t addr) {
    asm volatile(
        "ldmatrix.sync.aligned.m8n8.x4.trans.shared.b16 {%0,%1,%2,%3}, [%4];"
        : "=r"(r[0]), "=r"(r[1]), "=r"(r[2]), "=r"(r[3]) : "r"(addr));
}
__device__ __forceinline__ uint32_t pkhf(float a, float b) {
    __half2 h = __floats2half2_rn(a, b);
    return *(uint32_t*)&h;
}
__device__ __forceinline__ void split2h(float x, float y, uint32_t &hi, uint32_t &lo) {
    float hx = __half2float(__float2half_rn(x));
    float hy = __half2float(__float2half_rn(y));
    hi = pkhf(x, y);
    lo = pkhf(x - hx, y - hy);
}
__device__ __forceinline__ float ex2f(float x) {
    float r; asm("ex2.approx.ftz.f32 %0, %1;" : "=f"(r) : "f"(x)); return r;
}
__device__ __forceinline__ void cp16(uint32_t dst, const void* src) {
    asm volatile("cp.async.cg.shared.global [%0], [%1], 16;"
                 :: "r"(dst), "l"(src));
}
__device__ __forceinline__ void cpcommit() {
    asm volatile("cp.async.commit_group;" ::: "memory");
}
template<int N>
__device__ __forceinline__ void cpwait() {
    asm volatile("cp.async.wait_group %0;" :: "n"(N) : "memory");
}

#define SA 144
#define QSCALE 0.18033688f   // 0.125 * log2(e)

// ---------------------------------------------------------------------------
// Convert kernels: X -> fp16 hi/lo;  W -> single fp16
// ---------------------------------------------------------------------------
__global__ __launch_bounds__(256)
void conv_x(const float* __restrict__ x0, const float* __restrict__ x1,
            const float* __restrict__ x2)
{
    const float* src = (blockIdx.z == 0) ? x0 : (blockIdx.z == 1) ? x1 : x2;
    size_t off = (size_t)blockIdx.z * XN;
    size_t i4  = ((size_t)blockIdx.x * 256 + threadIdx.x) * 4;
    float4 v = *(const float4*)(src + i4);
    uint32_t h0, l0, h1, l1;
    split2h(v.x, v.y, h0, l0);
    split2h(v.z, v.w, h1, l1);
    *(uint2*)(g_xh + off + i4) = make_uint2(h0, h1);
    *(uint2*)(g_xl + off + i4) = make_uint2(l0, l1);
}

__global__ __launch_bounds__(256)
void conv_w(const float* __restrict__ w0, const float* __restrict__ w1,
            const float* __restrict__ w2, const float* __restrict__ w3)
{
    const float* src = (blockIdx.z == 0) ? w0 : (blockIdx.z == 1) ? w1
                     : (blockIdx.z == 2) ? w2 : w3;
    size_t off = (size_t)blockIdx.z * WN;
    size_t i4  = ((size_t)blockIdx.x * 256 + threadIdx.x) * 4;
    float4 v = *(const float4*)(src + i4);
    *(uint2*)(g_wh + off + i4) = make_uint2(pkhf(v.x, v.y), pkhf(v.z, v.w));
}

// ---------------------------------------------------------------------------
// Pipelined HMMA GEMM, fp16 A-split 2-pass, pass-major MMA ordering.
// C[4096,768] = A * W^T.  256 thr, tile 128x128, BK=64, double-buffered.
// smem per buffer: Ah | Al | Bh, each 128 x 144B -> GBUF = 55296.
// MODE 0: A = g_x(z) hi/lo, B = g_wh(z); epilogue -> fp16 q/k/v (q scaled).
// MODE 1: A = g_c hi/lo, B = g_wh(3); epilogue -> fp32 out.
// ---------------------------------------------------------------------------
#define GBUF 55296

template<int MODE>
__global__ __launch_bounds__(256)
void gemm_hf(float* __restrict__ outp)
{
    extern __shared__ char sm[];
    const uint32_t base = smem_u32(sm);

    const int tid  = threadIdx.x;
    const int warp = tid >> 5;
    const int lane = tid & 31;
    const int g    = lane >> 2;
    const int t    = lane & 3;
    const int wm   = (warp >> 2) * 64;
    const int wn   = (warp & 3) * 32;
    const int rowBase = blockIdx.y * 128;
    const int colBase = blockIdx.x * 128;
    const int z = blockIdx.z;

    const __half *Ah, *Al, *Bh;
    if (MODE == 0) {
        Ah = g_xh + (size_t)z * XN; Al = g_xl + (size_t)z * XN;
        Bh = g_wh + (size_t)z * WN;
    } else {
        Ah = g_ch; Al = g_cl;
        Bh = g_wh + (size_t)3 * WN;
    }

    const uint32_t laneA = (uint32_t)(((lane & 7) + ((lane >> 3) & 1) * 8) * SA
                                      + (lane >> 4) * 16);
    const uint32_t laneB = (uint32_t)(((lane & 7) + ((lane >> 4) & 1) * 8) * SA
                                      + ((lane >> 3) & 1) * 16);

    float acc[4][4][4];
    #pragma unroll
    for (int mi = 0; mi < 4; ++mi)
        #pragma unroll
        for (int ni = 0; ni < 4; ++ni)
            #pragma unroll
            for (int r = 0; r < 4; ++r) acc[mi][ni][r] = 0.f;

    // 3 arrays x 1024 segs / 256 thr = 12 cp per thread
    auto load_chunk = [&](int ch, int p) {
        const int k0 = ch * 64;
        uint32_t sb = base + p * GBUF;
        #pragma unroll
        for (int it = 0; it < 4; ++it) {
            int idx = tid + it * 256;
            int r   = idx >> 3;
            int sg  = idx & 7;
            uint32_t d = (uint32_t)(r * SA + sg * 16);
            cp16(sb +          d, Ah + (size_t)(rowBase + r) * DD + k0 + sg * 8);
            cp16(sb + 18432u + d, Al + (size_t)(rowBase + r) * DD + k0 + sg * 8);
            cp16(sb + 36864u + d, Bh + (size_t)(colBase + r) * DD + k0 + sg * 8);
        }
    };

    load_chunk(0, 0);
    cpcommit();

    for (int ch = 0; ch < 12; ++ch) {
        cpwait<0>();
        __syncthreads();
        if (ch < 11) { load_chunk(ch + 1, (ch + 1) & 1); cpcommit(); }

        const uint32_t uAh = base + (ch & 1) * GBUF;
        const uint32_t uAl = uAh + 18432u;
        const uint32_t uBh = uAh + 36864u;

        #pragma unroll
        for (int kt = 0; kt < 4; ++kt) {
            const uint32_t ko = (uint32_t)kt * 32u;
            uint32_t afh[4][4], afl[4][4];
            #pragma unroll
            for (int mi = 0; mi < 4; ++mi) {
                uint32_t ao = (uint32_t)((wm + mi * 16) * SA) + ko;
                ldmat4(afh[mi], uAh + ao + laneA);
                ldmat4(afl[mi], uAl + ao + laneA);
            }
            uint32_t bh[2][4];
            #pragma unroll
            for (int np = 0; np < 2; ++np)
                ldmat4(bh[np], uBh + (uint32_t)((wn + np * 16) * SA) + ko + laneB);

            // pass-major: acc reuse distance = 16 MMAs
            #pragma unroll
            for (int ni = 0; ni < 4; ++ni) {
                uint32_t b0 = bh[ni >> 1][(ni & 1) * 2];
                uint32_t b1 = bh[ni >> 1][(ni & 1) * 2 + 1];
                #pragma unroll
                for (int mi = 0; mi < 4; ++mi)
                    mma16816h(acc[mi][ni], afh[mi], b0, b1);
            }
            #pragma unroll
            for (int ni = 0; ni < 4; ++ni) {
                uint32_t b0 = bh[ni >> 1][(ni & 1) * 2];
                uint32_t b1 = bh[ni >> 1][(ni & 1) * 2 + 1];
                #pragma unroll
                for (int mi = 0; mi < 4; ++mi)
                    mma16816h(acc[mi][ni], afl[mi], b0, b1);
            }
        }
    }

    #pragma unroll
    for (int mi = 0; mi < 4; ++mi) {
        int r0 = rowBase + wm + mi * 16 + g;
        int r1 = r0 + 8;
        #pragma unroll
        for (int ni = 0; ni < 4; ++ni) {
            int col = colBase + wn + ni * 8 + 2 * t;
            if (MODE == 0) {
                int h = col >> 6, dk = col & 63;
                int b0 = r0 >> 11, s0 = r0 & (SS - 1);
                int b1 = r1 >> 11, s1 = r1 & (SS - 1);
                size_t i0 = (((size_t)b0 * HH + h) * SS + s0) * DKK + dk;
                size_t i1 = (((size_t)b1 * HH + h) * SS + s1) * DKK + dk;
                const float sc = (z == 0) ? QSCALE : 1.0f;
                __half* dst = (z == 0) ? g_qh : (z == 1) ? g_kh : g_vh;
                *(uint32_t*)(dst + i0) = pkhf(acc[mi][ni][0] * sc, acc[mi][ni][1] * sc);
                *(uint32_t*)(dst + i1) = pkhf(acc[mi][ni][2] * sc, acc[mi][ni][3] * sc);
            } else {
                *(float2*)(outp + (size_t)r0 * DD + col) =
                    make_float2(acc[mi][ni][0], acc[mi][ni][1]);
                *(float2*)(outp + (size_t)r1 * DD + col) =
                    make_float2(acc[mi][ni][2], acc[mi][ni][3]);
            }
        }
    }
}

// ---------------------------------------------------------------------------
// Flash attention (all-fp16 single-pass): 128 thr (4 warps), 64 q/CTA,
// 64-key tiles; softmax base-2; single __syncthreads per tile.
// Epilogue -> ctx fp16 hi/lo.  smem 46080B -> 4 CTAs/SM.
// ---------------------------------------------------------------------------
#define FBUF 18432
#define FQ   9216

__global__ __launch_bounds__(128, 4)
void flash_tc()
{
    extern __shared__ char fsm[];
    const uint32_t base = smem_u32(fsm);
    const uint32_t uQ = base;

    const int tid  = threadIdx.x;
    const int warp = tid >> 5;
    const int lane = tid & 31;
    const int g    = lane >> 2;
    const int t    = lane & 3;
    const int b    = blockIdx.z;
    const int h    = blockIdx.y;
    const int qb   = (gridDim.x - 1) - blockIdx.x;

    const size_t headOff = (size_t)(b * HH + h) * SS * DKK;

    const uint32_t laneA = (uint32_t)(((lane & 7) + ((lane >> 3) & 1) * 8) * SA
                                      + (lane >> 4) * 16);
    const uint32_t laneB = (uint32_t)(((lane & 7) + ((lane >> 4) & 1) * 8) * SA
                                      + ((lane >> 3) & 1) * 16);

    auto load_kv = [&](int kt_tile, int p) {
        uint32_t sb = base + FQ + p * FBUF;
        #pragma unroll
        for (int it = 0; it < 4; ++it) {
            int idx = tid + it * 128;
            int r   = idx >> 3;
            int sg  = idx & 7;
            size_t  s = headOff + (size_t)(kt_tile * 64 + r) * DKK + sg * 8;
            uint32_t d = (uint32_t)(r * SA + sg * 16);
            cp16(sb +         d, g_kh + s);
            cp16(sb + 9216u + d, g_vh + s);
        }
    };

    #pragma unroll
    for (int it = 0; it < 4; ++it) {
        int idx = tid + it * 128;
        int r   = idx >> 3;
        int sg  = idx & 7;
        cp16(uQ + (uint32_t)(r * SA + sg * 16),
             g_qh + headOff + (size_t)(qb * 64 + r) * DKK + sg * 8);
    }
    load_kv(0, 0);
    cpcommit();

    float accO[8][4];
    #pragma unroll
    for (int d = 0; d < 8; ++d)
        #pragma unroll
        for (int r = 0; r < 4; ++r) accO[d][r] = 0.f;
    float m0 = -1e30f, m1 = -1e30f, l0 = 0.f, l1 = 0.f;

    const int qrow = warp * 16 + g;
    const int ntl  = qb + 1;

    for (int ch = 0; ch < ntl; ++ch) {
        cpwait<0>();
        __syncthreads();
        if (ch < ntl - 1) { load_kv(ch + 1, (ch + 1) & 1); cpcommit(); }

        const uint32_t uK = base + FQ + (ch & 1) * FBUF;
        const uint32_t uV = uK + 9216u;

        float sacc[8][4];
        #pragma unroll
        for (int nt = 0; nt < 8; ++nt)
            #pragma unroll
            for (int r = 0; r < 4; ++r) sacc[nt][r] = 0.f;

        #pragma unroll
        for (int kt = 0; kt < 4; ++kt) {
            const uint32_t ko = (uint32_t)kt * 32u;
            uint32_t qa[4];
            ldmat4(qa, uQ + (uint32_t)(warp * 16 * SA) + ko + laneA);
            uint32_t kf[4][4];
            #pragma unroll
            for (int np = 0; np < 4; ++np)
                ldmat4(kf[np], uK + (uint32_t)(np * 16 * SA) + ko + laneB);
            #pragma unroll
            for (int nt = 0; nt < 8; ++nt)
                mma16816h(sacc[nt], qa,
                          kf[nt >> 1][(nt & 1) * 2],
                          kf[nt >> 1][(nt & 1) * 2 + 1]);
        }

        if (ch == qb) {
            #pragma unroll
            for (int nt = 0; nt < 8; ++nt) {
                int kc = nt * 8 + 2 * t;
                if (kc     > qrow)     sacc[nt][0] = -1e30f;
                if (kc + 1 > qrow)     sacc[nt][1] = -1e30f;
                if (kc     > qrow + 8) sacc[nt][2] = -1e30f;
                if (kc + 1 > qrow + 8) sacc[nt][3] = -1e30f;
            }
        }

        float mx0 = -1e30f, mx1 = -1e30f;
        #pragma unroll
        for (int nt = 0; nt < 8; ++nt) {
            mx0 = fmaxf(mx0, fmaxf(sacc[nt][0], sacc[nt][1]));
            mx1 = fmaxf(mx1, fmaxf(sacc[nt][2], sacc[nt][3]));
        }
        mx0 = fmaxf(mx0, __shfl_xor_sync(0xffffffff, mx0, 1));
        mx0 = fmaxf(mx0, __shfl_xor_sync(0xffffffff, mx0, 2));
        mx1 = fmaxf(mx1, __shfl_xor_sync(0xffffffff, mx1, 1));
        mx1 = fmaxf(mx1, __shfl_xor_sync(0xffffffff, mx1, 2));
        float mn0 = fmaxf(m0, mx0), mn1 = fmaxf(m1, mx1);
        float cr0 = ex2f(m0 - mn0), cr1 = ex2f(m1 - mn1);
        m0 = mn0; m1 = mn1;
        l0 *= cr0; l1 *= cr1;
        #pragma unroll
        for (int d = 0; d < 8; ++d) {
            accO[d][0] *= cr0; accO[d][1] *= cr0;
            accO[d][2] *= cr1; accO[d][3] *= cr1;
        }

        uint32_t pah[4][4];
        #pragma unroll
        for (int nt = 0; nt < 8; ++nt) {
            float p0 = ex2f(sacc[nt][0] - mn0);
            float p1 = ex2f(sacc[nt][1] - mn0);
            float p2 = ex2f(sacc[nt][2] - mn1);
            float p3 = ex2f(sacc[nt][3] - mn1);
            l0 += p0 + p1;
            l1 += p2 + p3;
            int kt = nt >> 1;
            if ((nt & 1) == 0) {
                pah[kt][0] = pkhf(p0, p1);
                pah[kt][1] = pkhf(p2, p3);
            } else {
                pah[kt][2] = pkhf(p0, p1);
                pah[kt][3] = pkhf(p2, p3);
            }
        }

        const int mat = lane >> 3;
        const int rr  = lane & 7;
        #pragma unroll
        for (int kt = 0; kt < 4; ++kt) {
            #pragma unroll
            for (int pr = 0; pr < 4; ++pr) {
                uint32_t off = (uint32_t)((kt * 16 + rr + (mat & 1) * 8) * SA)
                             + (uint32_t)((pr * 16 + (mat >> 1) * 8) * 2);
                uint32_t vv[4];
                ldmat4t(vv, uV + off);
                mma16816h(accO[2 * pr],     pah[kt], vv[0], vv[1]);
                mma16816h(accO[2 * pr + 1], pah[kt], vv[2], vv[3]);
            }
        }
    }

    l0 += __shfl_xor_sync(0xffffffff, l0, 1);
    l0 += __shfl_xor_sync(0xffffffff, l0, 2);
    l1 += __shfl_xor_sync(0xffffffff, l1, 1);
    l1 += __shfl_xor_sync(0xffffffff, l1, 2);
    float inv0 = 1.0f / l0, inv1 = 1.0f / l1;

    int q0 = qb * 64 + qrow;
    size_t base0 = ((size_t)b * SS + q0) * DD + h * DKK;
    size_t base1 = base0 + (size_t)8 * DD;
    #pragma unroll
    for (int d = 0; d < 8; ++d) {
        int col = d * 8 + 2 * t;
        uint32_t hi, lo;
        split2h(accO[d][0] * inv0, accO[d][1] * inv0, hi, lo);
        *(uint32_t*)(g_ch + base0 + col) = hi;
        *(uint32_t*)(g_cl + base0 + col) = lo;
        split2h(accO[d][2] * inv1, accO[d][3] * inv1, hi, lo);
        *(uint32_t*)(g_ch + base1 + col) = hi;
        *(uint32_t*)(g_cl + base1 + col) = lo;
    }
}

// ---------------------------------------------------------------------------
extern "C" void kernel_launch(void* const* d_in, const int* in_sizes, int n_in,
                              void* d_out, int out_size)
{
    (void)in_sizes; (void)n_in; (void)out_size;
    const float* Q  = (const float*)d_in[0];
    const float* K  = (const float*)d_in[1];
    const float* V  = (const float*)d_in[2];
    const float* Wq = (const float*)d_in[4];
    const float* Wk = (const float*)d_in[5];
    const float* Wv = (const float*)d_in[6];
    const float* Wo = (const float*)d_in[7];
    float* out = (float*)d_out;

    constexpr int GEMM_SMEM  = 2 * GBUF;      // 110592
    constexpr int FLASH_SMEM = FQ + 2 * FBUF; // 46080
    static bool attr_done = false;
    if (!attr_done) {
        cudaFuncSetAttribute(gemm_hf<0>,
                             cudaFuncAttributeMaxDynamicSharedMemorySize, GEMM_SMEM);
        cudaFuncSetAttribute(gemm_hf<1>,
                             cudaFuncAttributeMaxDynamicSharedMemorySize, GEMM_SMEM);
        cudaFuncSetAttribute(flash_tc,
                             cudaFuncAttributeMaxDynamicSharedMemorySize, FLASH_SMEM);
        attr_done = true;
    }

    conv_x<<<dim3(XN / 4 / 256, 1, 3), 256>>>(Q, K, V);
    conv_w<<<dim3(WN / 4 / 256, 1, 4), 256>>>(Wq, Wk, Wv, Wo);

    gemm_hf<0><<<dim3(DD / 128, (BB * SS) / 128, 3), 256, GEMM_SMEM>>>(nullptr);

    flash_tc<<<dim3(SS / 64, HH, BB), 128, FLASH_SMEM>>>();

    gemm_hf<1><<<dim3(DD / 128, (BB * SS) / 128, 1), 256, GEMM_SMEM>>>(out);
}

// round 11
// speedup vs baseline: 1.5203x; 1.5203x over previous
#include <cuda_runtime.h>
#include <cuda_bf16.h>
#include <cuda_fp16.h>
#include <math.h>
#include <stdint.h>

#define BB   2
#define SS   2048
#define DD   768
#define HH   12
#define DKK  64

#define XN 3145728   // 4096*768
#define WN 589824    // 768*768
#define HN 3145728   // BB*HH*SS*DKK
#define CN 3145728   // BB*SS*DD

// fp16 scratch (allocation-free)
__device__ __align__(128) __half g_xh[3 * XN];   // activations hi
__device__ __align__(128) __half g_xl[3 * XN];   // activations lo residual
__device__ __align__(128) __half g_wh[4 * WN];   // weights single fp16
__device__ __align__(128) __half g_qh[HN];       // q (pre-scaled by 0.125*log2e)
__device__ __align__(128) __half g_kh[HN];
__device__ __align__(128) __half g_vh[HN];
__device__ __align__(128) __half g_ch[CN];       // ctx hi
__device__ __align__(128) __half g_cl[CN];       // ctx lo residual

// ------------------------------ helpers -------------------------------------
__device__ __forceinline__ uint32_t smem_u32(const void* p) {
    return (uint32_t)__cvta_generic_to_shared(p);
}
__device__ __forceinline__ void mma16816h(float* c, const uint32_t* a,
                                          uint32_t b0, uint32_t b1) {
    asm volatile(
        "mma.sync.aligned.m16n8k16.row.col.f32.f16.f16.f32 "
        "{%0,%1,%2,%3}, {%4,%5,%6,%7}, {%8,%9}, {%0,%1,%2,%3};"
        : "+f"(c[0]), "+f"(c[1]), "+f"(c[2]), "+f"(c[3])
        : "r"(a[0]), "r"(a[1]), "r"(a[2]), "r"(a[3]), "r"(b0), "r"(b1));
}
__device__ __forceinline__ void ldmat4(uint32_t* r, uint32_t addr) {
    asm volatile(
        "ldmatrix.sync.aligned.m8n8.x4.shared.b16 {%0,%1,%2,%3}, [%4];"
        : "=r"(r[0]), "=r"(r[1]), "=r"(r[2]), "=r"(r[3]) : "r"(addr));
}
__device__ __forceinline__ void ldmat4t(uint32_t* r, uint32_t addr) {
    asm volatile(
        "ldmatrix.sync.aligned.m8n8.x4.trans.shared.b16 {%0,%1,%2,%3}, [%4];"
        : "=r"(r[0]), "=r"(r[1]), "=r"(r[2]), "=r"(r[3]) : "r"(addr));
}
__device__ __forceinline__ uint32_t pkhf(float a, float b) {
    __half2 h = __floats2half2_rn(a, b);
    return *(uint32_t*)&h;
}
__device__ __forceinline__ void split2h(float x, float y, uint32_t &hi, uint32_t &lo) {
    float hx = __half2float(__float2half_rn(x));
    float hy = __half2float(__float2half_rn(y));
    hi = pkhf(x, y);
    lo = pkhf(x - hx, y - hy);
}
__device__ __forceinline__ float ex2f(float x) {
    float r; asm("ex2.approx.ftz.f32 %0, %1;" : "=f"(r) : "f"(x)); return r;
}
// packed half2 2^x — ONE MUFU for two P entries
__device__ __forceinline__ uint32_t ex2h2(uint32_t x) {
    uint32_t r; asm("ex2.approx.f16x2 %0, %1;" : "=r"(r) : "r"(x)); return r;
}
__device__ __forceinline__ void cp16(uint32_t dst, const void* src) {
    asm volatile("cp.async.cg.shared.global [%0], [%1], 16;"
                 :: "r"(dst), "l"(src));
}
__device__ __forceinline__ void cpcommit() {
    asm volatile("cp.async.commit_group;" ::: "memory");
}
template<int N>
__device__ __forceinline__ void cpwait() {
    asm volatile("cp.async.wait_group %0;" :: "n"(N) : "memory");
}

#define SA 144
#define QSCALE 0.18033688f   // 0.125 * log2(e)
#define ONES2  0x3C003C00u   // half2(1.0, 1.0)

// ---------------------------------------------------------------------------
// Convert kernels: X -> fp16 hi/lo;  W -> single fp16
// ---------------------------------------------------------------------------
__global__ __launch_bounds__(256)
void conv_x(const float* __restrict__ x0, const float* __restrict__ x1,
            const float* __restrict__ x2)
{
    const float* src = (blockIdx.z == 0) ? x0 : (blockIdx.z == 1) ? x1 : x2;
    size_t off = (size_t)blockIdx.z * XN;
    size_t i4  = ((size_t)blockIdx.x * 256 + threadIdx.x) * 4;
    float4 v = *(const float4*)(src + i4);
    uint32_t h0, l0, h1, l1;
    split2h(v.x, v.y, h0, l0);
    split2h(v.z, v.w, h1, l1);
    *(uint2*)(g_xh + off + i4) = make_uint2(h0, h1);
    *(uint2*)(g_xl + off + i4) = make_uint2(l0, l1);
}

__global__ __launch_bounds__(256)
void conv_w(const float* __restrict__ w0, const float* __restrict__ w1,
            const float* __restrict__ w2, const float* __restrict__ w3)
{
    const float* src = (blockIdx.z == 0) ? w0 : (blockIdx.z == 1) ? w1
                     : (blockIdx.z == 2) ? w2 : w3;
    size_t off = (size_t)blockIdx.z * WN;
    size_t i4  = ((size_t)blockIdx.x * 256 + threadIdx.x) * 4;
    float4 v = *(const float4*)(src + i4);
    *(uint2*)(g_wh + off + i4) = make_uint2(pkhf(v.x, v.y), pkhf(v.z, v.w));
}

// ---------------------------------------------------------------------------
// Pipelined HMMA GEMM, fp16 A-split 2-pass, pass-major MMA ordering.
// ---------------------------------------------------------------------------
#define GBUF 55296

template<int MODE>
__global__ __launch_bounds__(256)
void gemm_hf(float* __restrict__ outp)
{
    extern __shared__ char sm[];
    const uint32_t base = smem_u32(sm);

    const int tid  = threadIdx.x;
    const int warp = tid >> 5;
    const int lane = tid & 31;
    const int g    = lane >> 2;
    const int t    = lane & 3;
    const int wm   = (warp >> 2) * 64;
    const int wn   = (warp & 3) * 32;
    const int rowBase = blockIdx.y * 128;
    const int colBase = blockIdx.x * 128;
    const int z = blockIdx.z;

    const __half *Ah, *Al, *Bh;
    if (MODE == 0) {
        Ah = g_xh + (size_t)z * XN; Al = g_xl + (size_t)z * XN;
        Bh = g_wh + (size_t)z * WN;
    } else {
        Ah = g_ch; Al = g_cl;
        Bh = g_wh + (size_t)3 * WN;
    }

    const uint32_t laneA = (uint32_t)(((lane & 7) + ((lane >> 3) & 1) * 8) * SA
                                      + (lane >> 4) * 16);
    const uint32_t laneB = (uint32_t)(((lane & 7) + ((lane >> 4) & 1) * 8) * SA
                                      + ((lane >> 3) & 1) * 16);

    float acc[4][4][4];
    #pragma unroll
    for (int mi = 0; mi < 4; ++mi)
        #pragma unroll
        for (int ni = 0; ni < 4; ++ni)
            #pragma unroll
            for (int r = 0; r < 4; ++r) acc[mi][ni][r] = 0.f;

    auto load_chunk = [&](int ch, int p) {
        const int k0 = ch * 64;
        uint32_t sb = base + p * GBUF;
        #pragma unroll
        for (int it = 0; it < 4; ++it) {
            int idx = tid + it * 256;
            int r   = idx >> 3;
            int sg  = idx & 7;
            uint32_t d = (uint32_t)(r * SA + sg * 16);
            cp16(sb +          d, Ah + (size_t)(rowBase + r) * DD + k0 + sg * 8);
            cp16(sb + 18432u + d, Al + (size_t)(rowBase + r) * DD + k0 + sg * 8);
            cp16(sb + 36864u + d, Bh + (size_t)(colBase + r) * DD + k0 + sg * 8);
        }
    };

    load_chunk(0, 0);
    cpcommit();

    for (int ch = 0; ch < 12; ++ch) {
        cpwait<0>();
        __syncthreads();
        if (ch < 11) { load_chunk(ch + 1, (ch + 1) & 1); cpcommit(); }

        const uint32_t uAh = base + (ch & 1) * GBUF;
        const uint32_t uAl = uAh + 18432u;
        const uint32_t uBh = uAh + 36864u;

        #pragma unroll
        for (int kt = 0; kt < 4; ++kt) {
            const uint32_t ko = (uint32_t)kt * 32u;
            uint32_t afh[4][4], afl[4][4];
            #pragma unroll
            for (int mi = 0; mi < 4; ++mi) {
                uint32_t ao = (uint32_t)((wm + mi * 16) * SA) + ko;
                ldmat4(afh[mi], uAh + ao + laneA);
                ldmat4(afl[mi], uAl + ao + laneA);
            }
            uint32_t bh[2][4];
            #pragma unroll
            for (int np = 0; np < 2; ++np)
                ldmat4(bh[np], uBh + (uint32_t)((wn + np * 16) * SA) + ko + laneB);

            #pragma unroll
            for (int ni = 0; ni < 4; ++ni) {
                uint32_t b0 = bh[ni >> 1][(ni & 1) * 2];
                uint32_t b1 = bh[ni >> 1][(ni & 1) * 2 + 1];
                #pragma unroll
                for (int mi = 0; mi < 4; ++mi)
                    mma16816h(acc[mi][ni], afh[mi], b0, b1);
            }
            #pragma unroll
            for (int ni = 0; ni < 4; ++ni) {
                uint32_t b0 = bh[ni >> 1][(ni & 1) * 2];
                uint32_t b1 = bh[ni >> 1][(ni & 1) * 2 + 1];
                #pragma unroll
                for (int mi = 0; mi < 4; ++mi)
                    mma16816h(acc[mi][ni], afl[mi], b0, b1);
            }
        }
    }

    #pragma unroll
    for (int mi = 0; mi < 4; ++mi) {
        int r0 = rowBase + wm + mi * 16 + g;
        int r1 = r0 + 8;
        #pragma unroll
        for (int ni = 0; ni < 4; ++ni) {
            int col = colBase + wn + ni * 8 + 2 * t;
            if (MODE == 0) {
                int h = col >> 6, dk = col & 63;
                int b0 = r0 >> 11, s0 = r0 & (SS - 1);
                int b1 = r1 >> 11, s1 = r1 & (SS - 1);
                size_t i0 = (((size_t)b0 * HH + h) * SS + s0) * DKK + dk;
                size_t i1 = (((size_t)b1 * HH + h) * SS + s1) * DKK + dk;
                const float sc = (z == 0) ? QSCALE : 1.0f;
                __half* dst = (z == 0) ? g_qh : (z == 1) ? g_kh : g_vh;
                *(uint32_t*)(dst + i0) = pkhf(acc[mi][ni][0] * sc, acc[mi][ni][1] * sc);
                *(uint32_t*)(dst + i1) = pkhf(acc[mi][ni][2] * sc, acc[mi][ni][3] * sc);
            } else {
                *(float2*)(outp + (size_t)r0 * DD + col) =
                    make_float2(acc[mi][ni][0], acc[mi][ni][1]);
                *(float2*)(outp + (size_t)r1 * DD + col) =
                    make_float2(acc[mi][ni][2], acc[mi][ni][3]);
            }
        }
    }
}

// ---------------------------------------------------------------------------
// Flash attention: 128 thr (4 warps), 64 q/CTA, 64-key tiles.
// S single fp16 pass; P via packed ex2.approx.f16x2 (16 MUFU vs 32);
// l via ones-column MMA (fp32, consistent with PV numerator, no shuffles).
// smem 46080B -> 4 CTAs/SM.
// ---------------------------------------------------------------------------
#define FBUF 18432
#define FQ   9216

__global__ __launch_bounds__(128, 4)
void flash_tc()
{
    extern __shared__ char fsm[];
    const uint32_t base = smem_u32(fsm);
    const uint32_t uQ = base;

    const int tid  = threadIdx.x;
    const int warp = tid >> 5;
    const int lane = tid & 31;
    const int g    = lane >> 2;
    const int t    = lane & 3;
    const int b    = blockIdx.z;
    const int h    = blockIdx.y;
    const int qb   = (gridDim.x - 1) - blockIdx.x;

    const size_t headOff = (size_t)(b * HH + h) * SS * DKK;

    const uint32_t laneA = (uint32_t)(((lane & 7) + ((lane >> 3) & 1) * 8) * SA
                                      + (lane >> 4) * 16);
    const uint32_t laneB = (uint32_t)(((lane & 7) + ((lane >> 4) & 1) * 8) * SA
                                      + ((lane >> 3) & 1) * 16);

    auto load_kv = [&](int kt_tile, int p) {
        uint32_t sb = base + FQ + p * FBUF;
        #pragma unroll
        for (int it = 0; it < 4; ++it) {
            int idx = tid + it * 128;
            int r   = idx >> 3;
            int sg  = idx & 7;
            size_t  s = headOff + (size_t)(kt_tile * 64 + r) * DKK + sg * 8;
            uint32_t d = (uint32_t)(r * SA + sg * 16);
            cp16(sb +         d, g_kh + s);
            cp16(sb + 9216u + d, g_vh + s);
        }
    };

    #pragma unroll
    for (int it = 0; it < 4; ++it) {
        int idx = tid + it * 128;
        int r   = idx >> 3;
        int sg  = idx & 7;
        cp16(uQ + (uint32_t)(r * SA + sg * 16),
             g_qh + headOff + (size_t)(qb * 64 + r) * DKK + sg * 8);
    }
    load_kv(0, 0);
    cpcommit();

    float accO[8][4];
    #pragma unroll
    for (int d = 0; d < 8; ++d)
        #pragma unroll
        for (int r = 0; r < 4; ++r) accO[d][r] = 0.f;
    float lacc[4] = {0.f, 0.f, 0.f, 0.f};   // row-sum accumulator (ones-MMA)
    float m0 = -1e30f, m1 = -1e30f;

    const int qrow = warp * 16 + g;
    const int ntl  = qb + 1;

    for (int ch = 0; ch < ntl; ++ch) {
        cpwait<0>();
        __syncthreads();
        if (ch < ntl - 1) { load_kv(ch + 1, (ch + 1) & 1); cpcommit(); }

        const uint32_t uK = base + FQ + (ch & 1) * FBUF;
        const uint32_t uV = uK + 9216u;

        float sacc[8][4];
        #pragma unroll
        for (int nt = 0; nt < 8; ++nt)
            #pragma unroll
            for (int r = 0; r < 4; ++r) sacc[nt][r] = 0.f;

        #pragma unroll
        for (int kt = 0; kt < 4; ++kt) {
            const uint32_t ko = (uint32_t)kt * 32u;
            uint32_t qa[4];
            ldmat4(qa, uQ + (uint32_t)(warp * 16 * SA) + ko + laneA);
            uint32_t kf[4][4];
            #pragma unroll
            for (int np = 0; np < 4; ++np)
                ldmat4(kf[np], uK + (uint32_t)(np * 16 * SA) + ko + laneB);
            #pragma unroll
            for (int nt = 0; nt < 8; ++nt)
                mma16816h(sacc[nt], qa,
                          kf[nt >> 1][(nt & 1) * 2],
                          kf[nt >> 1][(nt & 1) * 2 + 1]);
        }

        if (ch == qb) {
            #pragma unroll
            for (int nt = 0; nt < 8; ++nt) {
                int kc = nt * 8 + 2 * t;
                if (kc     > qrow)     sacc[nt][0] = -1e30f;
                if (kc + 1 > qrow)     sacc[nt][1] = -1e30f;
                if (kc     > qrow + 8) sacc[nt][2] = -1e30f;
                if (kc + 1 > qrow + 8) sacc[nt][3] = -1e30f;
            }
        }

        float mx0 = -1e30f, mx1 = -1e30f;
        #pragma unroll
        for (int nt = 0; nt < 8; ++nt) {
            mx0 = fmaxf(mx0, fmaxf(sacc[nt][0], sacc[nt][1]));
            mx1 = fmaxf(mx1, fmaxf(sacc[nt][2], sacc[nt][3]));
        }
        mx0 = fmaxf(mx0, __shfl_xor_sync(0xffffffff, mx0, 1));
        mx0 = fmaxf(mx0, __shfl_xor_sync(0xffffffff, mx0, 2));
        mx1 = fmaxf(mx1, __shfl_xor_sync(0xffffffff, mx1, 1));
        mx1 = fmaxf(mx1, __shfl_xor_sync(0xffffffff, mx1, 2));
        float mn0 = fmaxf(m0, mx0), mn1 = fmaxf(m1, mx1);
        float cr0 = ex2f(m0 - mn0), cr1 = ex2f(m1 - mn1);
        m0 = mn0; m1 = mn1;
        lacc[0] *= cr0; lacc[1] *= cr0;
        lacc[2] *= cr1; lacc[3] *= cr1;
        #pragma unroll
        for (int d = 0; d < 8; ++d) {
            accO[d][0] *= cr0; accO[d][1] *= cr0;
            accO[d][2] *= cr1; accO[d][3] *= cr1;
        }

        // ---- P = 2^(S-m): packed half2 exp (one MUFU per pair) ----
        uint32_t pah[4][4];
        #pragma unroll
        for (int nt = 0; nt < 8; ++nt) {
            uint32_t u01 = ex2h2(pkhf(sacc[nt][0] - mn0, sacc[nt][1] - mn0));
            uint32_t u23 = ex2h2(pkhf(sacc[nt][2] - mn1, sacc[nt][3] - mn1));
            int kt = nt >> 1;
            if ((nt & 1) == 0) { pah[kt][0] = u01; pah[kt][1] = u23; }
            else               { pah[kt][2] = u01; pah[kt][3] = u23; }
        }

        // ---- l row-sums via ones-MMA (fp32 accumulate) ----
        #pragma unroll
        for (int kt = 0; kt < 4; ++kt)
            mma16816h(lacc, pah[kt], ONES2, ONES2);

        // ---- O += P V ----
        const int mat = lane >> 3;
        const int rr  = lane & 7;
        #pragma unroll
        for (int kt = 0; kt < 4; ++kt) {
            #pragma unroll
            for (int pr = 0; pr < 4; ++pr) {
                uint32_t off = (uint32_t)((kt * 16 + rr + (mat & 1) * 8) * SA)
                             + (uint32_t)((pr * 16 + (mat >> 1) * 8) * 2);
                uint32_t vv[4];
                ldmat4t(vv, uV + off);
                mma16816h(accO[2 * pr],     pah[kt], vv[0], vv[1]);
                mma16816h(accO[2 * pr + 1], pah[kt], vv[2], vv[3]);
            }
        }
    }

    // l is already the full row sum (MMA reduced over all keys)
    float inv0 = 1.0f / lacc[0], inv1 = 1.0f / lacc[2];

    int q0 = qb * 64 + qrow;
    size_t base0 = ((size_t)b * SS + q0) * DD + h * DKK;
    size_t base1 = base0 + (size_t)8 * DD;
    #pragma unroll
    for (int d = 0; d < 8; ++d) {
        int col = d * 8 + 2 * t;
        uint32_t hi, lo;
        split2h(accO[d][0] * inv0, accO[d][1] * inv0, hi, lo);
        *(uint32_t*)(g_ch + base0 + col) = hi;
        *(uint32_t*)(g_cl + base0 + col) = lo;
        split2h(accO[d][2] * inv1, accO[d][3] * inv1, hi, lo);
        *(uint32_t*)(g_ch + base1 + col) = hi;
        *(uint32_t*)(g_cl + base1 + col) = lo;
    }
}

// ---------------------------------------------------------------------------
extern "C" void kernel_launch(void* const* d_in, const int* in_sizes, int n_in,
                              void* d_out, int out_size)
{
    (void)in_sizes; (void)n_in; (void)out_size;
    const float* Q  = (const float*)d_in[0];
    const float* K  = (const float*)d_in[1];
    const float* V  = (const float*)d_in[2];
    const float* Wq = (const float*)d_in[4];
    const float* Wk = (const float*)d_in[5];
    const float* Wv = (const float*)d_in[6];
    const float* Wo = (const float*)d_in[7];
    float* out = (float*)d_out;

    constexpr int GEMM_SMEM  = 2 * GBUF;      // 110592
    constexpr int FLASH_SMEM = FQ + 2 * FBUF; // 46080
    static bool attr_done = false;
    if (!attr_done) {
        cudaFuncSetAttribute(gemm_hf<0>,
                             cudaFuncAttributeMaxDynamicSharedMemorySize, GEMM_SMEM);
        cudaFuncSetAttribute(gemm_hf<1>,
                             cudaFuncAttributeMaxDynamicSharedMemorySize, GEMM_SMEM);
        cudaFuncSetAttribute(flash_tc,
                             cudaFuncAttributeMaxDynamicSharedMemorySize, FLASH_SMEM);
        attr_done = true;
    }

    conv_x<<<dim3(XN / 4 / 256, 1, 3), 256>>>(Q, K, V);
    conv_w<<<dim3(WN / 4 / 256, 1, 4), 256>>>(Wq, Wk, Wv, Wo);

    gemm_hf<0><<<dim3(DD / 128, (BB * SS) / 128, 3), 256, GEMM_SMEM>>>(nullptr);

    flash_tc<<<dim3(SS / 64, HH, BB), 128, FLASH_SMEM>>>();

    gemm_hf<1><<<dim3(DD / 128, (BB * SS) / 128, 1), 256, GEMM_SMEM>>>(out);
}

// round 12
// speedup vs baseline: 1.8156x; 1.1942x over previous
#include <cuda_runtime.h>
#include <cuda_bf16.h>
#include <cuda_fp16.h>
#include <math.h>
#include <stdint.h>

#define BB   2
#define SS   2048
#define DD   768
#define HH   12
#define DKK  64

#define XN 3145728   // 4096*768
#define WN 589824    // 768*768
#define HN 3145728   // BB*HH*SS*DKK
#define CN 3145728   // BB*SS*DD

// fp16 scratch (allocation-free)
__device__ __align__(128) __half g_xh[3 * XN];   // activations (single fp16)
__device__ __align__(128) __half g_wh[4 * WN];   // weights (single fp16)
__device__ __align__(128) __half g_qh[HN];       // q (pre-scaled by 0.125*log2e)
__device__ __align__(128) __half g_kh[HN];
__device__ __align__(128) __half g_vh[HN];
__device__ __align__(128) __half g_ch[CN];       // ctx hi
__device__ __align__(128) __half g_cl[CN];       // ctx lo residual

// ------------------------------ helpers -------------------------------------
__device__ __forceinline__ uint32_t smem_u32(const void* p) {
    return (uint32_t)__cvta_generic_to_shared(p);
}
__device__ __forceinline__ void mma16816h(float* c, const uint32_t* a,
                                          uint32_t b0, uint32_t b1) {
    asm volatile(
        "mma.sync.aligned.m16n8k16.row.col.f32.f16.f16.f32 "
        "{%0,%1,%2,%3}, {%4,%5,%6,%7}, {%8,%9}, {%0,%1,%2,%3};"
        : "+f"(c[0]), "+f"(c[1]), "+f"(c[2]), "+f"(c[3])
        : "r"(a[0]), "r"(a[1]), "r"(a[2]), "r"(a[3]), "r"(b0), "r"(b1));
}
__device__ __forceinline__ void ldmat4(uint32_t* r, uint32_t addr) {
    asm volatile(
        "ldmatrix.sync.aligned.m8n8.x4.shared.b16 {%0,%1,%2,%3}, [%4];"
        : "=r"(r[0]), "=r"(r[1]), "=r"(r[2]), "=r"(r[3]) : "r"(addr));
}
__device__ __forceinline__ void ldmat4t(uint32_t* r, uint32_t addr) {
    asm volatile(
        "ldmatrix.sync.aligned.m8n8.x4.trans.shared.b16 {%0,%1,%2,%3}, [%4];"
        : "=r"(r[0]), "=r"(r[1]), "=r"(r[2]), "=r"(r[3]) : "r"(addr));
}
__device__ __forceinline__ uint32_t pkhf(float a, float b) {
    __half2 h = __floats2half2_rn(a, b);
    return *(uint32_t*)&h;
}
__device__ __forceinline__ void split2h(float x, float y, uint32_t &hi, uint32_t &lo) {
    float hx = __half2float(__float2half_rn(x));
    float hy = __half2float(__float2half_rn(y));
    hi = pkhf(x, y);
    lo = pkhf(x - hx, y - hy);
}
__device__ __forceinline__ float ex2f(float x) {
    float r; asm("ex2.approx.ftz.f32 %0, %1;" : "=f"(r) : "f"(x)); return r;
}
__device__ __forceinline__ uint32_t ex2h2(uint32_t x) {
    uint32_t r; asm("ex2.approx.f16x2 %0, %1;" : "=r"(r) : "r"(x)); return r;
}
__device__ __forceinline__ void cp16(uint32_t dst, const void* src) {
    asm volatile("cp.async.cg.shared.global [%0], [%1], 16;"
                 :: "r"(dst), "l"(src));
}
__device__ __forceinline__ void cpcommit() {
    asm volatile("cp.async.commit_group;" ::: "memory");
}
template<int N>
__device__ __forceinline__ void cpwait() {
    asm volatile("cp.async.wait_group %0;" :: "n"(N) : "memory");
}

#define SA 144
#define QSCALE 0.18033688f   // 0.125 * log2(e)
#define ONES2  0x3C003C00u   // half2(1.0, 1.0)

// ---------------------------------------------------------------------------
// Convert kernels: X -> single fp16;  W -> single fp16
// ---------------------------------------------------------------------------
__global__ __launch_bounds__(256)
void conv_x(const float* __restrict__ x0, const float* __restrict__ x1,
            const float* __restrict__ x2)
{
    const float* src = (blockIdx.z == 0) ? x0 : (blockIdx.z == 1) ? x1 : x2;
    size_t off = (size_t)blockIdx.z * XN;
    size_t i4  = ((size_t)blockIdx.x * 256 + threadIdx.x) * 4;
    float4 v = *(const float4*)(src + i4);
    *(uint2*)(g_xh + off + i4) = make_uint2(pkhf(v.x, v.y), pkhf(v.z, v.w));
}

__global__ __launch_bounds__(256)
void conv_w(const float* __restrict__ w0, const float* __restrict__ w1,
            const float* __restrict__ w2, const float* __restrict__ w3)
{
    const float* src = (blockIdx.z == 0) ? w0 : (blockIdx.z == 1) ? w1
                     : (blockIdx.z == 2) ? w2 : w3;
    size_t off = (size_t)blockIdx.z * WN;
    size_t i4  = ((size_t)blockIdx.x * 256 + threadIdx.x) * 4;
    float4 v = *(const float4*)(src + i4);
    *(uint2*)(g_wh + off + i4) = make_uint2(pkhf(v.x, v.y), pkhf(v.z, v.w));
}

// ---------------------------------------------------------------------------
// Pipelined HMMA GEMM.
// MODE 0 (projections): single-pass fp16 (A=X fp16, B=W fp16), NA=1.
//   Epilogue rounds to fp16 q/k/v anyway -> residual pass wasted; dropped.
// MODE 1 (output proj): A = ctx hi/lo 2-pass (feeds fp32 output), NA=2.
// smem per buffer: NA*A + B arrays of 128x144B.
// ---------------------------------------------------------------------------
#define GARR 18432

template<int MODE>
__global__ __launch_bounds__(256)
void gemm_hf(float* __restrict__ outp)
{
    constexpr int NA   = (MODE == 0) ? 1 : 2;
    constexpr uint32_t GBUF = (NA + 1) * GARR;

    extern __shared__ char sm[];
    const uint32_t base = smem_u32(sm);

    const int tid  = threadIdx.x;
    const int warp = tid >> 5;
    const int lane = tid & 31;
    const int g    = lane >> 2;
    const int t    = lane & 3;
    const int wm   = (warp >> 2) * 64;
    const int wn   = (warp & 3) * 32;
    const int rowBase = blockIdx.y * 128;
    const int colBase = blockIdx.x * 128;
    const int z = blockIdx.z;

    const __half *Ah, *Al, *Bh;
    if (MODE == 0) {
        Ah = g_xh + (size_t)z * XN; Al = nullptr;
        Bh = g_wh + (size_t)z * WN;
    } else {
        Ah = g_ch; Al = g_cl;
        Bh = g_wh + (size_t)3 * WN;
    }

    const uint32_t laneA = (uint32_t)(((lane & 7) + ((lane >> 3) & 1) * 8) * SA
                                      + (lane >> 4) * 16);
    const uint32_t laneB = (uint32_t)(((lane & 7) + ((lane >> 4) & 1) * 8) * SA
                                      + ((lane >> 3) & 1) * 16);

    float acc[4][4][4];
    #pragma unroll
    for (int mi = 0; mi < 4; ++mi)
        #pragma unroll
        for (int ni = 0; ni < 4; ++ni)
            #pragma unroll
            for (int r = 0; r < 4; ++r) acc[mi][ni][r] = 0.f;

    auto load_chunk = [&](int ch, int p) {
        const int k0 = ch * 64;
        uint32_t sb = base + p * GBUF;
        #pragma unroll
        for (int it = 0; it < 4; ++it) {
            int idx = tid + it * 256;
            int r   = idx >> 3;
            int sg  = idx & 7;
            uint32_t d = (uint32_t)(r * SA + sg * 16);
            cp16(sb + d, Ah + (size_t)(rowBase + r) * DD + k0 + sg * 8);
            if (MODE == 1)
                cp16(sb + GARR + d, Al + (size_t)(rowBase + r) * DD + k0 + sg * 8);
            cp16(sb + NA * GARR + d, Bh + (size_t)(colBase + r) * DD + k0 + sg * 8);
        }
    };

    load_chunk(0, 0);
    cpcommit();

    for (int ch = 0; ch < 12; ++ch) {
        cpwait<0>();
        __syncthreads();
        if (ch < 11) { load_chunk(ch + 1, (ch + 1) & 1); cpcommit(); }

        const uint32_t uAh = base + (ch & 1) * GBUF;
        const uint32_t uAl = uAh + GARR;           // valid only for MODE 1
        const uint32_t uBh = uAh + NA * GARR;

        #pragma unroll
        for (int kt = 0; kt < 4; ++kt) {
            const uint32_t ko = (uint32_t)kt * 32u;
            uint32_t afh[4][4], afl[4][4];
            #pragma unroll
            for (int mi = 0; mi < 4; ++mi) {
                uint32_t ao = (uint32_t)((wm + mi * 16) * SA) + ko;
                ldmat4(afh[mi], uAh + ao + laneA);
                if (MODE == 1) ldmat4(afl[mi], uAl + ao + laneA);
            }
            uint32_t bh[2][4];
            #pragma unroll
            for (int np = 0; np < 2; ++np)
                ldmat4(bh[np], uBh + (uint32_t)((wn + np * 16) * SA) + ko + laneB);

            #pragma unroll
            for (int ni = 0; ni < 4; ++ni) {
                uint32_t b0 = bh[ni >> 1][(ni & 1) * 2];
                uint32_t b1 = bh[ni >> 1][(ni & 1) * 2 + 1];
                #pragma unroll
                for (int mi = 0; mi < 4; ++mi)
                    mma16816h(acc[mi][ni], afh[mi], b0, b1);
            }
            if (MODE == 1) {
                #pragma unroll
                for (int ni = 0; ni < 4; ++ni) {
                    uint32_t b0 = bh[ni >> 1][(ni & 1) * 2];
                    uint32_t b1 = bh[ni >> 1][(ni & 1) * 2 + 1];
                    #pragma unroll
                    for (int mi = 0; mi < 4; ++mi)
                        mma16816h(acc[mi][ni], afl[mi], b0, b1);
                }
            }
        }
    }

    #pragma unroll
    for (int mi = 0; mi < 4; ++mi) {
        int r0 = rowBase + wm + mi * 16 + g;
        int r1 = r0 + 8;
        #pragma unroll
        for (int ni = 0; ni < 4; ++ni) {
            int col = colBase + wn + ni * 8 + 2 * t;
            if (MODE == 0) {
                int h = col >> 6, dk = col & 63;
                int b0 = r0 >> 11, s0 = r0 & (SS - 1);
                int b1 = r1 >> 11, s1 = r1 & (SS - 1);
                size_t i0 = (((size_t)b0 * HH + h) * SS + s0) * DKK + dk;
                size_t i1 = (((size_t)b1 * HH + h) * SS + s1) * DKK + dk;
                const float sc = (z == 0) ? QSCALE : 1.0f;
                __half* dst = (z == 0) ? g_qh : (z == 1) ? g_kh : g_vh;
                *(uint32_t*)(dst + i0) = pkhf(acc[mi][ni][0] * sc, acc[mi][ni][1] * sc);
                *(uint32_t*)(dst + i1) = pkhf(acc[mi][ni][2] * sc, acc[mi][ni][3] * sc);
            } else {
                *(float2*)(outp + (size_t)r0 * DD + col) =
                    make_float2(acc[mi][ni][0], acc[mi][ni][1]);
                *(float2*)(outp + (size_t)r1 * DD + col) =
                    make_float2(acc[mi][ni][2], acc[mi][ni][3]);
            }
        }
    }
}

// ---------------------------------------------------------------------------
// Flash attention (unchanged from R11): 128 thr, 64 q/CTA, 64-key tiles;
// S single fp16 pass; P via ex2.approx.f16x2; l via ones-MMA.
// ---------------------------------------------------------------------------
#define FBUF 18432
#define FQ   9216

__global__ __launch_bounds__(128, 4)
void flash_tc()
{
    extern __shared__ char fsm[];
    const uint32_t base = smem_u32(fsm);
    const uint32_t uQ = base;

    const int tid  = threadIdx.x;
    const int warp = tid >> 5;
    const int lane = tid & 31;
    const int g    = lane >> 2;
    const int t    = lane & 3;
    const int b    = blockIdx.z;
    const int h    = blockIdx.y;
    const int qb   = (gridDim.x - 1) - blockIdx.x;

    const size_t headOff = (size_t)(b * HH + h) * SS * DKK;

    const uint32_t laneA = (uint32_t)(((lane & 7) + ((lane >> 3) & 1) * 8) * SA
                                      + (lane >> 4) * 16);
    const uint32_t laneB = (uint32_t)(((lane & 7) + ((lane >> 4) & 1) * 8) * SA
                                      + ((lane >> 3) & 1) * 16);

    auto load_kv = [&](int kt_tile, int p) {
        uint32_t sb = base + FQ + p * FBUF;
        #pragma unroll
        for (int it = 0; it < 4; ++it) {
            int idx = tid + it * 128;
            int r   = idx >> 3;
            int sg  = idx & 7;
            size_t  s = headOff + (size_t)(kt_tile * 64 + r) * DKK + sg * 8;
            uint32_t d = (uint32_t)(r * SA + sg * 16);
            cp16(sb +         d, g_kh + s);
            cp16(sb + 9216u + d, g_vh + s);
        }
    };

    #pragma unroll
    for (int it = 0; it < 4; ++it) {
        int idx = tid + it * 128;
        int r   = idx >> 3;
        int sg  = idx & 7;
        cp16(uQ + (uint32_t)(r * SA + sg * 16),
             g_qh + headOff + (size_t)(qb * 64 + r) * DKK + sg * 8);
    }
    load_kv(0, 0);
    cpcommit();

    float accO[8][4];
    #pragma unroll
    for (int d = 0; d < 8; ++d)
        #pragma unroll
        for (int r = 0; r < 4; ++r) accO[d][r] = 0.f;
    float lacc[4] = {0.f, 0.f, 0.f, 0.f};
    float m0 = -1e30f, m1 = -1e30f;

    const int qrow = warp * 16 + g;
    const int ntl  = qb + 1;

    for (int ch = 0; ch < ntl; ++ch) {
        cpwait<0>();
        __syncthreads();
        if (ch < ntl - 1) { load_kv(ch + 1, (ch + 1) & 1); cpcommit(); }

        const uint32_t uK = base + FQ + (ch & 1) * FBUF;
        const uint32_t uV = uK + 9216u;

        float sacc[8][4];
        #pragma unroll
        for (int nt = 0; nt < 8; ++nt)
            #pragma unroll
            for (int r = 0; r < 4; ++r) sacc[nt][r] = 0.f;

        #pragma unroll
        for (int kt = 0; kt < 4; ++kt) {
            const uint32_t ko = (uint32_t)kt * 32u;
            uint32_t qa[4];
            ldmat4(qa, uQ + (uint32_t)(warp * 16 * SA) + ko + laneA);
            uint32_t kf[4][4];
            #pragma unroll
            for (int np = 0; np < 4; ++np)
                ldmat4(kf[np], uK + (uint32_t)(np * 16 * SA) + ko + laneB);
            #pragma unroll
            for (int nt = 0; nt < 8; ++nt)
                mma16816h(sacc[nt], qa,
                          kf[nt >> 1][(nt & 1) * 2],
                          kf[nt >> 1][(nt & 1) * 2 + 1]);
        }

        if (ch == qb) {
            #pragma unroll
            for (int nt = 0; nt < 8; ++nt) {
                int kc = nt * 8 + 2 * t;
                if (kc     > qrow)     sacc[nt][0] = -1e30f;
                if (kc + 1 > qrow)     sacc[nt][1] = -1e30f;
                if (kc     > qrow + 8) sacc[nt][2] = -1e30f;
                if (kc + 1 > qrow + 8) sacc[nt][3] = -1e30f;
            }
        }

        float mx0 = -1e30f, mx1 = -1e30f;
        #pragma unroll
        for (int nt = 0; nt < 8; ++nt) {
            mx0 = fmaxf(mx0, fmaxf(sacc[nt][0], sacc[nt][1]));
            mx1 = fmaxf(mx1, fmaxf(sacc[nt][2], sacc[nt][3]));
        }
        mx0 = fmaxf(mx0, __shfl_xor_sync(0xffffffff, mx0, 1));
        mx0 = fmaxf(mx0, __shfl_xor_sync(0xffffffff, mx0, 2));
        mx1 = fmaxf(mx1, __shfl_xor_sync(0xffffffff, mx1, 1));
        mx1 = fmaxf(mx1, __shfl_xor_sync(0xffffffff, mx1, 2));
        float mn0 = fmaxf(m0, mx0), mn1 = fmaxf(m1, mx1);
        float cr0 = ex2f(m0 - mn0), cr1 = ex2f(m1 - mn1);
        m0 = mn0; m1 = mn1;
        lacc[0] *= cr0; lacc[1] *= cr0;
        lacc[2] *= cr1; lacc[3] *= cr1;
        #pragma unroll
        for (int d = 0; d < 8; ++d) {
            accO[d][0] *= cr0; accO[d][1] *= cr0;
            accO[d][2] *= cr1; accO[d][3] *= cr1;
        }

        uint32_t pah[4][4];
        #pragma unroll
        for (int nt = 0; nt < 8; ++nt) {
            uint32_t u01 = ex2h2(pkhf(sacc[nt][0] - mn0, sacc[nt][1] - mn0));
            uint32_t u23 = ex2h2(pkhf(sacc[nt][2] - mn1, sacc[nt][3] - mn1));
            int kt = nt >> 1;
            if ((nt & 1) == 0) { pah[kt][0] = u01; pah[kt][1] = u23; }
            else               { pah[kt][2] = u01; pah[kt][3] = u23; }
        }

        #pragma unroll
        for (int kt = 0; kt < 4; ++kt)
            mma16816h(lacc, pah[kt], ONES2, ONES2);

        const int mat = lane >> 3;
        const int rr  = lane & 7;
        #pragma unroll
        for (int kt = 0; kt < 4; ++kt) {
            #pragma unroll
            for (int pr = 0; pr < 4; ++pr) {
                uint32_t off = (uint32_t)((kt * 16 + rr + (mat & 1) * 8) * SA)
                             + (uint32_t)((pr * 16 + (mat >> 1) * 8) * 2);
                uint32_t vv[4];
                ldmat4t(vv, uV + off);
                mma16816h(accO[2 * pr],     pah[kt], vv[0], vv[1]);
                mma16816h(accO[2 * pr + 1], pah[kt], vv[2], vv[3]);
            }
        }
    }

    float inv0 = 1.0f / lacc[0], inv1 = 1.0f / lacc[2];

    int q0 = qb * 64 + qrow;
    size_t base0 = ((size_t)b * SS + q0) * DD + h * DKK;
    size_t base1 = base0 + (size_t)8 * DD;
    #pragma unroll
    for (int d = 0; d < 8; ++d) {
        int col = d * 8 + 2 * t;
        uint32_t hi, lo;
        split2h(accO[d][0] * inv0, accO[d][1] * inv0, hi, lo);
        *(uint32_t*)(g_ch + base0 + col) = hi;
        *(uint32_t*)(g_cl + base0 + col) = lo;
        split2h(accO[d][2] * inv1, accO[d][3] * inv1, hi, lo);
        *(uint32_t*)(g_ch + base1 + col) = hi;
        *(uint32_t*)(g_cl + base1 + col) = lo;
    }
}

// ---------------------------------------------------------------------------
extern "C" void kernel_launch(void* const* d_in, const int* in_sizes, int n_in,
                              void* d_out, int out_size)
{
    (void)in_sizes; (void)n_in; (void)out_size;
    const float* Q  = (const float*)d_in[0];
    const float* K  = (const float*)d_in[1];
    const float* V  = (const float*)d_in[2];
    const float* Wq = (const float*)d_in[4];
    const float* Wk = (const float*)d_in[5];
    const float* Wv = (const float*)d_in[6];
    const float* Wo = (const float*)d_in[7];
    float* out = (float*)d_out;

    constexpr int GEMM0_SMEM = 2 * (2 * GARR);  // 73728
    constexpr int GEMM1_SMEM = 2 * (3 * GARR);  // 110592
    constexpr int FLASH_SMEM = FQ + 2 * FBUF;   // 46080
    static bool attr_done = false;
    if (!attr_done) {
        cudaFuncSetAttribute(gemm_hf<0>,
                             cudaFuncAttributeMaxDynamicSharedMemorySize, GEMM0_SMEM);
        cudaFuncSetAttribute(gemm_hf<1>,
                             cudaFuncAttributeMaxDynamicSharedMemorySize, GEMM1_SMEM);
        cudaFuncSetAttribute(flash_tc,
                             cudaFuncAttributeMaxDynamicSharedMemorySize, FLASH_SMEM);
        attr_done = true;
    }

    conv_x<<<dim3(XN / 4 / 256, 1, 3), 256>>>(Q, K, V);
    conv_w<<<dim3(WN / 4 / 256, 1, 4), 256>>>(Wq, Wk, Wv, Wo);

    gemm_hf<0><<<dim3(DD / 128, (BB * SS) / 128, 3), 256, GEMM0_SMEM>>>(nullptr);

    flash_tc<<<dim3(SS / 64, HH, BB), 128, FLASH_SMEM>>>();

    gemm_hf<1><<<dim3(DD / 128, (BB * SS) / 128, 1), 256, GEMM1_SMEM>>>(out);
}

// round 13
// speedup vs baseline: 2.0199x; 1.1125x over previous
#include <cuda_runtime.h>
#include <cuda_bf16.h>
#include <cuda_fp16.h>
#include <math.h>
#include <stdint.h>

#define BB   2
#define SS   2048
#define DD   768
#define HH   12
#define DKK  64

#define XN 3145728   // 4096*768
#define WN 589824    // 768*768
#define HN 3145728   // BB*HH*SS*DKK
#define CN 3145728   // BB*SS*DD

// fp16 scratch (allocation-free)
__device__ __align__(128) __half g_xh[3 * XN];   // activations (single fp16)
__device__ __align__(128) __half g_wh[4 * WN];   // weights (single fp16)
__device__ __align__(128) __half g_qh[HN];       // q (pre-scaled by 0.125*log2e)
__device__ __align__(128) __half g_kh[HN];
__device__ __align__(128) __half g_vh[HN];
__device__ __align__(128) __half g_ch[CN];       // ctx (single fp16)

// ------------------------------ helpers -------------------------------------
__device__ __forceinline__ uint32_t smem_u32(const void* p) {
    return (uint32_t)__cvta_generic_to_shared(p);
}
__device__ __forceinline__ void mma16816h(float* c, const uint32_t* a,
                                          uint32_t b0, uint32_t b1) {
    asm volatile(
        "mma.sync.aligned.m16n8k16.row.col.f32.f16.f16.f32 "
        "{%0,%1,%2,%3}, {%4,%5,%6,%7}, {%8,%9}, {%0,%1,%2,%3};"
        : "+f"(c[0]), "+f"(c[1]), "+f"(c[2]), "+f"(c[3])
        : "r"(a[0]), "r"(a[1]), "r"(a[2]), "r"(a[3]), "r"(b0), "r"(b1));
}
__device__ __forceinline__ void ldmat4(uint32_t* r, uint32_t addr) {
    asm volatile(
        "ldmatrix.sync.aligned.m8n8.x4.shared.b16 {%0,%1,%2,%3}, [%4];"
        : "=r"(r[0]), "=r"(r[1]), "=r"(r[2]), "=r"(r[3]) : "r"(addr));
}
__device__ __forceinline__ void ldmat4t(uint32_t* r, uint32_t addr) {
    asm volatile(
        "ldmatrix.sync.aligned.m8n8.x4.trans.shared.b16 {%0,%1,%2,%3}, [%4];"
        : "=r"(r[0]), "=r"(r[1]), "=r"(r[2]), "=r"(r[3]) : "r"(addr));
}
__device__ __forceinline__ uint32_t pkhf(float a, float b) {
    __half2 h = __floats2half2_rn(a, b);
    return *(uint32_t*)&h;
}
__device__ __forceinline__ float ex2f(float x) {
    float r; asm("ex2.approx.ftz.f32 %0, %1;" : "=f"(r) : "f"(x)); return r;
}
__device__ __forceinline__ uint32_t ex2h2(uint32_t x) {
    uint32_t r; asm("ex2.approx.f16x2 %0, %1;" : "=r"(r) : "r"(x)); return r;
}
__device__ __forceinline__ void cp16(uint32_t dst, const void* src) {
    asm volatile("cp.async.cg.shared.global [%0], [%1], 16;"
                 :: "r"(dst), "l"(src));
}
__device__ __forceinline__ void cpcommit() {
    asm volatile("cp.async.commit_group;" ::: "memory");
}
template<int N>
__device__ __forceinline__ void cpwait() {
    asm volatile("cp.async.wait_group %0;" :: "n"(N) : "memory");
}

#define SA 144
#define QSCALE 0.18033688f   // 0.125 * log2(e)
#define ONES2  0x3C003C00u   // half2(1.0, 1.0)

// ---------------------------------------------------------------------------
// Convert kernels: X -> single fp16;  W -> single fp16
// ---------------------------------------------------------------------------
__global__ __launch_bounds__(256)
void conv_x(const float* __restrict__ x0, const float* __restrict__ x1,
            const float* __restrict__ x2)
{
    const float* src = (blockIdx.z == 0) ? x0 : (blockIdx.z == 1) ? x1 : x2;
    size_t off = (size_t)blockIdx.z * XN;
    size_t i4  = ((size_t)blockIdx.x * 256 + threadIdx.x) * 4;
    float4 v = *(const float4*)(src + i4);
    *(uint2*)(g_xh + off + i4) = make_uint2(pkhf(v.x, v.y), pkhf(v.z, v.w));
}

__global__ __launch_bounds__(256)
void conv_w(const float* __restrict__ w0, const float* __restrict__ w1,
            const float* __restrict__ w2, const float* __restrict__ w3)
{
    const float* src = (blockIdx.z == 0) ? w0 : (blockIdx.z == 1) ? w1
                     : (blockIdx.z == 2) ? w2 : w3;
    size_t off = (size_t)blockIdx.z * WN;
    size_t i4  = ((size_t)blockIdx.x * 256 + threadIdx.x) * 4;
    float4 v = *(const float4*)(src + i4);
    *(uint2*)(g_wh + off + i4) = make_uint2(pkhf(v.x, v.y), pkhf(v.z, v.w));
}

// ---------------------------------------------------------------------------
// Pipelined HMMA GEMM, single-pass fp16 (both modes).
// MODE 0: A = g_xh(z), B = g_wh(z); epilogue -> fp16 q/k/v (q scaled).
// MODE 1: A = g_ch,    B = g_wh(3); epilogue -> fp32 out.
// smem per buffer: A + B arrays of 128x144B -> GBUF = 36864; 3 CTAs/SM.
// ---------------------------------------------------------------------------
#define GARR 18432
#define GBUF (2 * GARR)

template<int MODE>
__global__ __launch_bounds__(256)
void gemm_hf(float* __restrict__ outp)
{
    extern __shared__ char sm[];
    const uint32_t base = smem_u32(sm);

    const int tid  = threadIdx.x;
    const int warp = tid >> 5;
    const int lane = tid & 31;
    const int g    = lane >> 2;
    const int t    = lane & 3;
    const int wm   = (warp >> 2) * 64;
    const int wn   = (warp & 3) * 32;
    const int rowBase = blockIdx.y * 128;
    const int colBase = blockIdx.x * 128;
    const int z = blockIdx.z;

    const __half *Ah, *Bh;
    if (MODE == 0) {
        Ah = g_xh + (size_t)z * XN;
        Bh = g_wh + (size_t)z * WN;
    } else {
        Ah = g_ch;
        Bh = g_wh + (size_t)3 * WN;
    }

    const uint32_t laneA = (uint32_t)(((lane & 7) + ((lane >> 3) & 1) * 8) * SA
                                      + (lane >> 4) * 16);
    const uint32_t laneB = (uint32_t)(((lane & 7) + ((lane >> 4) & 1) * 8) * SA
                                      + ((lane >> 3) & 1) * 16);

    float acc[4][4][4];
    #pragma unroll
    for (int mi = 0; mi < 4; ++mi)
        #pragma unroll
        for (int ni = 0; ni < 4; ++ni)
            #pragma unroll
            for (int r = 0; r < 4; ++r) acc[mi][ni][r] = 0.f;

    auto load_chunk = [&](int ch, int p) {
        const int k0 = ch * 64;
        uint32_t sb = base + p * GBUF;
        #pragma unroll
        for (int it = 0; it < 4; ++it) {
            int idx = tid + it * 256;
            int r   = idx >> 3;
            int sg  = idx & 7;
            uint32_t d = (uint32_t)(r * SA + sg * 16);
            cp16(sb +        d, Ah + (size_t)(rowBase + r) * DD + k0 + sg * 8);
            cp16(sb + GARR + d, Bh + (size_t)(colBase + r) * DD + k0 + sg * 8);
        }
    };

    load_chunk(0, 0);
    cpcommit();

    for (int ch = 0; ch < 12; ++ch) {
        cpwait<0>();
        __syncthreads();
        if (ch < 11) { load_chunk(ch + 1, (ch + 1) & 1); cpcommit(); }

        const uint32_t uAh = base + (ch & 1) * GBUF;
        const uint32_t uBh = uAh + GARR;

        #pragma unroll
        for (int kt = 0; kt < 4; ++kt) {
            const uint32_t ko = (uint32_t)kt * 32u;
            uint32_t afh[4][4];
            #pragma unroll
            for (int mi = 0; mi < 4; ++mi)
                ldmat4(afh[mi], uAh + (uint32_t)((wm + mi * 16) * SA) + ko + laneA);
            uint32_t bh[2][4];
            #pragma unroll
            for (int np = 0; np < 2; ++np)
                ldmat4(bh[np], uBh + (uint32_t)((wn + np * 16) * SA) + ko + laneB);

            #pragma unroll
            for (int ni = 0; ni < 4; ++ni) {
                uint32_t b0 = bh[ni >> 1][(ni & 1) * 2];
                uint32_t b1 = bh[ni >> 1][(ni & 1) * 2 + 1];
                #pragma unroll
                for (int mi = 0; mi < 4; ++mi)
                    mma16816h(acc[mi][ni], afh[mi], b0, b1);
            }
        }
    }

    #pragma unroll
    for (int mi = 0; mi < 4; ++mi) {
        int r0 = rowBase + wm + mi * 16 + g;
        int r1 = r0 + 8;
        #pragma unroll
        for (int ni = 0; ni < 4; ++ni) {
            int col = colBase + wn + ni * 8 + 2 * t;
            if (MODE == 0) {
                int h = col >> 6, dk = col & 63;
                int b0 = r0 >> 11, s0 = r0 & (SS - 1);
                int b1 = r1 >> 11, s1 = r1 & (SS - 1);
                size_t i0 = (((size_t)b0 * HH + h) * SS + s0) * DKK + dk;
                size_t i1 = (((size_t)b1 * HH + h) * SS + s1) * DKK + dk;
                const float sc = (z == 0) ? QSCALE : 1.0f;
                __half* dst = (z == 0) ? g_qh : (z == 1) ? g_kh : g_vh;
                *(uint32_t*)(dst + i0) = pkhf(acc[mi][ni][0] * sc, acc[mi][ni][1] * sc);
                *(uint32_t*)(dst + i1) = pkhf(acc[mi][ni][2] * sc, acc[mi][ni][3] * sc);
            } else {
                *(float2*)(outp + (size_t)r0 * DD + col) =
                    make_float2(acc[mi][ni][0], acc[mi][ni][1]);
                *(float2*)(outp + (size_t)r1 * DD + col) =
                    make_float2(acc[mi][ni][2], acc[mi][ni][3]);
            }
        }
    }
}

// ---------------------------------------------------------------------------
// Flash attention: 128 thr (4 warps), 64 q/CTA, 64-key tiles.
// S single fp16 pass; lazy rescale (skip when no lane's max moved);
// P via ex2.approx.f16x2; l via ones-MMA; epilogue -> single fp16 ctx.
// smem 46080B -> 4 CTAs/SM.
// ---------------------------------------------------------------------------
#define FBUF 18432
#define FQ   9216

__global__ __launch_bounds__(128, 4)
void flash_tc()
{
    extern __shared__ char fsm[];
    const uint32_t base = smem_u32(fsm);
    const uint32_t uQ = base;

    const int tid  = threadIdx.x;
    const int warp = tid >> 5;
    const int lane = tid & 31;
    const int g    = lane >> 2;
    const int t    = lane & 3;
    const int b    = blockIdx.z;
    const int h    = blockIdx.y;
    const int qb   = (gridDim.x - 1) - blockIdx.x;

    const size_t headOff = (size_t)(b * HH + h) * SS * DKK;

    const uint32_t laneA = (uint32_t)(((lane & 7) + ((lane >> 3) & 1) * 8) * SA
                                      + (lane >> 4) * 16);
    const uint32_t laneB = (uint32_t)(((lane & 7) + ((lane >> 4) & 1) * 8) * SA
                                      + ((lane >> 3) & 1) * 16);

    auto load_kv = [&](int kt_tile, int p) {
        uint32_t sb = base + FQ + p * FBUF;
        #pragma unroll
        for (int it = 0; it < 4; ++it) {
            int idx = tid + it * 128;
            int r   = idx >> 3;
            int sg  = idx & 7;
            size_t  s = headOff + (size_t)(kt_tile * 64 + r) * DKK + sg * 8;
            uint32_t d = (uint32_t)(r * SA + sg * 16);
            cp16(sb +         d, g_kh + s);
            cp16(sb + 9216u + d, g_vh + s);
        }
    };

    #pragma unroll
    for (int it = 0; it < 4; ++it) {
        int idx = tid + it * 128;
        int r   = idx >> 3;
        int sg  = idx & 7;
        cp16(uQ + (uint32_t)(r * SA + sg * 16),
             g_qh + headOff + (size_t)(qb * 64 + r) * DKK + sg * 8);
    }
    load_kv(0, 0);
    cpcommit();

    float accO[8][4];
    #pragma unroll
    for (int d = 0; d < 8; ++d)
        #pragma unroll
        for (int r = 0; r < 4; ++r) accO[d][r] = 0.f;
    float lacc[4] = {0.f, 0.f, 0.f, 0.f};
    float m0 = -1e30f, m1 = -1e30f;

    const int qrow = warp * 16 + g;
    const int ntl  = qb + 1;

    for (int ch = 0; ch < ntl; ++ch) {
        cpwait<0>();
        __syncthreads();
        if (ch < ntl - 1) { load_kv(ch + 1, (ch + 1) & 1); cpcommit(); }

        const uint32_t uK = base + FQ + (ch & 1) * FBUF;
        const uint32_t uV = uK + 9216u;

        float sacc[8][4];
        #pragma unroll
        for (int nt = 0; nt < 8; ++nt)
            #pragma unroll
            for (int r = 0; r < 4; ++r) sacc[nt][r] = 0.f;

        #pragma unroll
        for (int kt = 0; kt < 4; ++kt) {
            const uint32_t ko = (uint32_t)kt * 32u;
            uint32_t qa[4];
            ldmat4(qa, uQ + (uint32_t)(warp * 16 * SA) + ko + laneA);
            uint32_t kf[4][4];
            #pragma unroll
            for (int np = 0; np < 4; ++np)
                ldmat4(kf[np], uK + (uint32_t)(np * 16 * SA) + ko + laneB);
            #pragma unroll
            for (int nt = 0; nt < 8; ++nt)
                mma16816h(sacc[nt], qa,
                          kf[nt >> 1][(nt & 1) * 2],
                          kf[nt >> 1][(nt & 1) * 2 + 1]);
        }

        if (ch == qb) {
            #pragma unroll
            for (int nt = 0; nt < 8; ++nt) {
                int kc = nt * 8 + 2 * t;
                if (kc     > qrow)     sacc[nt][0] = -1e30f;
                if (kc + 1 > qrow)     sacc[nt][1] = -1e30f;
                if (kc     > qrow + 8) sacc[nt][2] = -1e30f;
                if (kc + 1 > qrow + 8) sacc[nt][3] = -1e30f;
            }
        }

        // ---- tile max ----
        float mx0 = -1e30f, mx1 = -1e30f;
        #pragma unroll
        for (int nt = 0; nt < 8; ++nt) {
            mx0 = fmaxf(mx0, fmaxf(sacc[nt][0], sacc[nt][1]));
            mx1 = fmaxf(mx1, fmaxf(sacc[nt][2], sacc[nt][3]));
        }
        mx0 = fmaxf(mx0, __shfl_xor_sync(0xffffffff, mx0, 1));
        mx0 = fmaxf(mx0, __shfl_xor_sync(0xffffffff, mx0, 2));
        mx1 = fmaxf(mx1, __shfl_xor_sync(0xffffffff, mx1, 1));
        mx1 = fmaxf(mx1, __shfl_xor_sync(0xffffffff, mx1, 2));

        // ---- lazy rescale: only when some lane's running max moved ----
        bool upd = (mx0 > m0) || (mx1 > m1);
        if (__any_sync(0xffffffff, upd)) {
            float mn0 = fmaxf(m0, mx0), mn1 = fmaxf(m1, mx1);
            float cr0 = ex2f(m0 - mn0), cr1 = ex2f(m1 - mn1);
            m0 = mn0; m1 = mn1;
            lacc[0] *= cr0; lacc[1] *= cr0;
            lacc[2] *= cr1; lacc[3] *= cr1;
            #pragma unroll
            for (int d = 0; d < 8; ++d) {
                accO[d][0] *= cr0; accO[d][1] *= cr0;
                accO[d][2] *= cr1; accO[d][3] *= cr1;
            }
        }

        // ---- P = 2^(S-m) as fp16 A-fragments ----
        uint32_t pah[4][4];
        #pragma unroll
        for (int nt = 0; nt < 8; ++nt) {
            uint32_t u01 = ex2h2(pkhf(sacc[nt][0] - m0, sacc[nt][1] - m0));
            uint32_t u23 = ex2h2(pkhf(sacc[nt][2] - m1, sacc[nt][3] - m1));
            int kt = nt >> 1;
            if ((nt & 1) == 0) { pah[kt][0] = u01; pah[kt][1] = u23; }
            else               { pah[kt][2] = u01; pah[kt][3] = u23; }
        }

        // ---- l row-sums via ones-MMA ----
        #pragma unroll
        for (int kt = 0; kt < 4; ++kt)
            mma16816h(lacc, pah[kt], ONES2, ONES2);

        // ---- O += P V ----
        const int mat = lane >> 3;
        const int rr  = lane & 7;
        #pragma unroll
        for (int kt = 0; kt < 4; ++kt) {
            #pragma unroll
            for (int pr = 0; pr < 4; ++pr) {
                uint32_t off = (uint32_t)((kt * 16 + rr + (mat & 1) * 8) * SA)
                             + (uint32_t)((pr * 16 + (mat >> 1) * 8) * 2);
                uint32_t vv[4];
                ldmat4t(vv, uV + off);
                mma16816h(accO[2 * pr],     pah[kt], vv[0], vv[1]);
                mma16816h(accO[2 * pr + 1], pah[kt], vv[2], vv[3]);
            }
        }
    }

    float inv0 = 1.0f / lacc[0], inv1 = 1.0f / lacc[2];

    int q0 = qb * 64 + qrow;
    size_t base0 = ((size_t)b * SS + q0) * DD + h * DKK;
    size_t base1 = base0 + (size_t)8 * DD;
    #pragma unroll
    for (int d = 0; d < 8; ++d) {
        int col = d * 8 + 2 * t;
        *(uint32_t*)(g_ch + base0 + col) =
            pkhf(accO[d][0] * inv0, accO[d][1] * inv0);
        *(uint32_t*)(g_ch + base1 + col) =
            pkhf(accO[d][2] * inv1, accO[d][3] * inv1);
    }
}

// ---------------------------------------------------------------------------
extern "C" void kernel_launch(void* const* d_in, const int* in_sizes, int n_in,
                              void* d_out, int out_size)
{
    (void)in_sizes; (void)n_in; (void)out_size;
    const float* Q  = (const float*)d_in[0];
    const float* K  = (const float*)d_in[1];
    const float* V  = (const float*)d_in[2];
    const float* Wq = (const float*)d_in[4];
    const float* Wk = (const float*)d_in[5];
    const float* Wv = (const float*)d_in[6];
    const float* Wo = (const float*)d_in[7];
    float* out = (float*)d_out;

    constexpr int GEMM_SMEM  = 2 * GBUF;      // 73728
    constexpr int FLASH_SMEM = FQ + 2 * FBUF; // 46080
    static bool attr_done = false;
    if (!attr_done) {
        cudaFuncSetAttribute(gemm_hf<0>,
                             cudaFuncAttributeMaxDynamicSharedMemorySize, GEMM_SMEM);
        cudaFuncSetAttribute(gemm_hf<1>,
                             cudaFuncAttributeMaxDynamicSharedMemorySize, GEMM_SMEM);
        cudaFuncSetAttribute(flash_tc,
                             cudaFuncAttributeMaxDynamicSharedMemorySize, FLASH_SMEM);
        attr_done = true;
    }

    conv_x<<<dim3(XN / 4 / 256, 1, 3), 256>>>(Q, K, V);
    conv_w<<<dim3(WN / 4 / 256, 1, 4), 256>>>(Wq, Wk, Wv, Wo);

    gemm_hf<0><<<dim3(DD / 128, (BB * SS) / 128, 3), 256, GEMM_SMEM>>>(nullptr);

    flash_tc<<<dim3(SS / 64, HH, BB), 128, FLASH_SMEM>>>();

    gemm_hf<1><<<dim3(DD / 128, (BB * SS) / 128, 1), 256, GEMM_SMEM>>>(out);
}

// round 14
// speedup vs baseline: 2.1302x; 1.0546x over previous
#include <cuda_runtime.h>
#include <cuda_bf16.h>
#include <cuda_fp16.h>
#include <math.h>
#include <stdint.h>

#define BB   2
#define SS   2048
#define DD   768
#define HH   12
#define DKK  64

#define XN 3145728   // 4096*768
#define WN 589824    // 768*768
#define HN 3145728   // BB*HH*SS*DKK
#define CN 3145728   // BB*SS*DD

// fp16 scratch (allocation-free)
__device__ __align__(128) __half g_xh[3 * XN];   // activations (single fp16)
__device__ __align__(128) __half g_wh[4 * WN];   // weights (single fp16)
__device__ __align__(128) __half g_qh[HN];       // q (pre-scaled by 0.125*log2e)
__device__ __align__(128) __half g_kh[HN];
__device__ __align__(128) __half g_vh[HN];
__device__ __align__(128) __half g_ch[CN];       // ctx (single fp16)

// ------------------------------ helpers -------------------------------------
__device__ __forceinline__ uint32_t smem_u32(const void* p) {
    return (uint32_t)__cvta_generic_to_shared(p);
}
__device__ __forceinline__ void mma16816h(float* c, const uint32_t* a,
                                          uint32_t b0, uint32_t b1) {
    asm volatile(
        "mma.sync.aligned.m16n8k16.row.col.f32.f16.f16.f32 "
        "{%0,%1,%2,%3}, {%4,%5,%6,%7}, {%8,%9}, {%0,%1,%2,%3};"
        : "+f"(c[0]), "+f"(c[1]), "+f"(c[2]), "+f"(c[3])
        : "r"(a[0]), "r"(a[1]), "r"(a[2]), "r"(a[3]), "r"(b0), "r"(b1));
}
__device__ __forceinline__ void ldmat4(uint32_t* r, uint32_t addr) {
    asm volatile(
        "ldmatrix.sync.aligned.m8n8.x4.shared.b16 {%0,%1,%2,%3}, [%4];"
        : "=r"(r[0]), "=r"(r[1]), "=r"(r[2]), "=r"(r[3]) : "r"(addr));
}
__device__ __forceinline__ void ldmat4t(uint32_t* r, uint32_t addr) {
    asm volatile(
        "ldmatrix.sync.aligned.m8n8.x4.trans.shared.b16 {%0,%1,%2,%3}, [%4];"
        : "=r"(r[0]), "=r"(r[1]), "=r"(r[2]), "=r"(r[3]) : "r"(addr));
}
__device__ __forceinline__ uint32_t pkhf(float a, float b) {
    __half2 h = __floats2half2_rn(a, b);
    return *(uint32_t*)&h;
}
__device__ __forceinline__ float ex2f(float x) {
    float r; asm("ex2.approx.ftz.f32 %0, %1;" : "=f"(r) : "f"(x)); return r;
}
__device__ __forceinline__ uint32_t ex2h2(uint32_t x) {
    uint32_t r; asm("ex2.approx.f16x2 %0, %1;" : "=r"(r) : "r"(x)); return r;
}
__device__ __forceinline__ void cp16(uint32_t dst, const void* src) {
    asm volatile("cp.async.cg.shared.global [%0], [%1], 16;"
                 :: "r"(dst), "l"(src));
}
__device__ __forceinline__ void cpcommit() {
    asm volatile("cp.async.commit_group;" ::: "memory");
}
template<int N>
__device__ __forceinline__ void cpwait() {
    asm volatile("cp.async.wait_group %0;" :: "n"(N) : "memory");
}

#define SA 144
#define QSCALE 0.18033688f   // 0.125 * log2(e)
#define ONES2  0x3C003C00u   // half2(1.0, 1.0)

// ---------------------------------------------------------------------------
// Single fused convert kernel: all X and W tensors -> fp16, one flat grid.
// Total float4 elements: (3*XN + 4*WN)/4 = 2949120 -> 11520 blocks of 256.
// ---------------------------------------------------------------------------
__global__ __launch_bounds__(256)
void conv_all(const float* __restrict__ x0, const float* __restrict__ x1,
              const float* __restrict__ x2, const float* __restrict__ w0,
              const float* __restrict__ w1, const float* __restrict__ w2,
              const float* __restrict__ w3)
{
    size_t gi = ((size_t)blockIdx.x * 256 + threadIdx.x) * 4;
    if (gi < (size_t)3 * XN) {
        int z = (int)(gi / XN);
        size_t off = gi - (size_t)z * XN;
        const float* src = (z == 0) ? x0 : (z == 1) ? x1 : x2;
        float4 v = *(const float4*)(src + off);
        *(uint2*)(g_xh + gi) = make_uint2(pkhf(v.x, v.y), pkhf(v.z, v.w));
    } else {
        size_t gw = gi - (size_t)3 * XN;
        int z = (int)(gw / WN);
        size_t off = gw - (size_t)z * WN;
        const float* src = (z == 0) ? w0 : (z == 1) ? w1 : (z == 2) ? w2 : w3;
        float4 v = *(const float4*)(src + off);
        *(uint2*)(g_wh + gw) = make_uint2(pkhf(v.x, v.y), pkhf(v.z, v.w));
    }
}

// ---------------------------------------------------------------------------
// Projections GEMM (unchanged from R13 MODE 0): single-pass fp16,
// 128x128 tile, BK=64, double-buffered; epilogue -> fp16 q/k/v (q scaled).
// ---------------------------------------------------------------------------
#define GARR 18432
#define GBUF (2 * GARR)

__global__ __launch_bounds__(256)
void gemm_proj()
{
    extern __shared__ char sm[];
    const uint32_t base = smem_u32(sm);

    const int tid  = threadIdx.x;
    const int warp = tid >> 5;
    const int lane = tid & 31;
    const int g    = lane >> 2;
    const int t    = lane & 3;
    const int wm   = (warp >> 2) * 64;
    const int wn   = (warp & 3) * 32;
    const int rowBase = blockIdx.y * 128;
    const int colBase = blockIdx.x * 128;
    const int z = blockIdx.z;

    const __half* Ah = g_xh + (size_t)z * XN;
    const __half* Bh = g_wh + (size_t)z * WN;

    const uint32_t laneA = (uint32_t)(((lane & 7) + ((lane >> 3) & 1) * 8) * SA
                                      + (lane >> 4) * 16);
    const uint32_t laneB = (uint32_t)(((lane & 7) + ((lane >> 4) & 1) * 8) * SA
                                      + ((lane >> 3) & 1) * 16);

    float acc[4][4][4];
    #pragma unroll
    for (int mi = 0; mi < 4; ++mi)
        #pragma unroll
        for (int ni = 0; ni < 4; ++ni)
            #pragma unroll
            for (int r = 0; r < 4; ++r) acc[mi][ni][r] = 0.f;

    auto load_chunk = [&](int ch, int p) {
        const int k0 = ch * 64;
        uint32_t sb = base + p * GBUF;
        #pragma unroll
        for (int it = 0; it < 4; ++it) {
            int idx = tid + it * 256;
            int r   = idx >> 3;
            int sg  = idx & 7;
            uint32_t d = (uint32_t)(r * SA + sg * 16);
            cp16(sb +        d, Ah + (size_t)(rowBase + r) * DD + k0 + sg * 8);
            cp16(sb + GARR + d, Bh + (size_t)(colBase + r) * DD + k0 + sg * 8);
        }
    };

    load_chunk(0, 0);
    cpcommit();

    for (int ch = 0; ch < 12; ++ch) {
        cpwait<0>();
        __syncthreads();
        if (ch < 11) { load_chunk(ch + 1, (ch + 1) & 1); cpcommit(); }

        const uint32_t uAh = base + (ch & 1) * GBUF;
        const uint32_t uBh = uAh + GARR;

        #pragma unroll
        for (int kt = 0; kt < 4; ++kt) {
            const uint32_t ko = (uint32_t)kt * 32u;
            uint32_t afh[4][4];
            #pragma unroll
            for (int mi = 0; mi < 4; ++mi)
                ldmat4(afh[mi], uAh + (uint32_t)((wm + mi * 16) * SA) + ko + laneA);
            uint32_t bh[2][4];
            #pragma unroll
            for (int np = 0; np < 2; ++np)
                ldmat4(bh[np], uBh + (uint32_t)((wn + np * 16) * SA) + ko + laneB);

            #pragma unroll
            for (int ni = 0; ni < 4; ++ni) {
                uint32_t b0 = bh[ni >> 1][(ni & 1) * 2];
                uint32_t b1 = bh[ni >> 1][(ni & 1) * 2 + 1];
                #pragma unroll
                for (int mi = 0; mi < 4; ++mi)
                    mma16816h(acc[mi][ni], afh[mi], b0, b1);
            }
        }
    }

    #pragma unroll
    for (int mi = 0; mi < 4; ++mi) {
        int r0 = rowBase + wm + mi * 16 + g;
        int r1 = r0 + 8;
        #pragma unroll
        for (int ni = 0; ni < 4; ++ni) {
            int col = colBase + wn + ni * 8 + 2 * t;
            int h = col >> 6, dk = col & 63;
            int b0 = r0 >> 11, s0 = r0 & (SS - 1);
            int b1 = r1 >> 11, s1 = r1 & (SS - 1);
            size_t i0 = (((size_t)b0 * HH + h) * SS + s0) * DKK + dk;
            size_t i1 = (((size_t)b1 * HH + h) * SS + s1) * DKK + dk;
            const float sc = (z == 0) ? QSCALE : 1.0f;
            __half* dst = (z == 0) ? g_qh : (z == 1) ? g_kh : g_vh;
            *(uint32_t*)(dst + i0) = pkhf(acc[mi][ni][0] * sc, acc[mi][ni][1] * sc);
            *(uint32_t*)(dst + i1) = pkhf(acc[mi][ni][2] * sc, acc[mi][ni][3] * sc);
        }
    }
}

// ---------------------------------------------------------------------------
// Output GEMM: out[4096,768] = ctx[4096,768] * Wo[768,768]^T, fp32 out.
// 128x64 tile (384 CTAs -> 1.3 waves instead of 0.65), BK=64, single-pass.
// Warp grid 4(M)x2(N): each warp 32 rows x 32 cols -> acc[2][4][4].
// smem per buffer: A 18432 + B 9216 = 27648; double -> 55296.
// ---------------------------------------------------------------------------
#define OBARR 9216
#define OBUF  (GARR + OBARR)

__global__ __launch_bounds__(256)
void gemm_out(float* __restrict__ outp)
{
    extern __shared__ char sm[];
    const uint32_t base = smem_u32(sm);

    const int tid  = threadIdx.x;
    const int warp = tid >> 5;
    const int lane = tid & 31;
    const int g    = lane >> 2;
    const int t    = lane & 3;
    const int wm   = (warp >> 1) * 32;   // 4 M-groups of 32 rows (2 m16 tiles)
    const int wn   = (warp & 1) * 32;    // 2 N-groups of 32 cols (4 n8 tiles)
    const int rowBase = blockIdx.y * 128;
    const int colBase = blockIdx.x * 64;

    const __half* Ah = g_ch;
    const __half* Bh = g_wh + (size_t)3 * WN;

    const uint32_t laneA = (uint32_t)(((lane & 7) + ((lane >> 3) & 1) * 8) * SA
                                      + (lane >> 4) * 16);
    const uint32_t laneB = (uint32_t)(((lane & 7) + ((lane >> 4) & 1) * 8) * SA
                                      + ((lane >> 3) & 1) * 16);

    float acc[2][4][4];
    #pragma unroll
    for (int mi = 0; mi < 2; ++mi)
        #pragma unroll
        for (int ni = 0; ni < 4; ++ni)
            #pragma unroll
            for (int r = 0; r < 4; ++r) acc[mi][ni][r] = 0.f;

    auto load_chunk = [&](int ch, int p) {
        const int k0 = ch * 64;
        uint32_t sb = base + p * OBUF;
        // A: 128 rows x 8 segs = 1024
        #pragma unroll
        for (int it = 0; it < 4; ++it) {
            int idx = tid + it * 256;
            int r   = idx >> 3;
            int sg  = idx & 7;
            cp16(sb + (uint32_t)(r * SA + sg * 16),
                 Ah + (size_t)(rowBase + r) * DD + k0 + sg * 8);
        }
        // B: 64 rows x 8 segs = 512
        #pragma unroll
        for (int it = 0; it < 2; ++it) {
            int idx = tid + it * 256;
            int r   = idx >> 3;
            int sg  = idx & 7;
            cp16(sb + GARR + (uint32_t)(r * SA + sg * 16),
                 Bh + (size_t)(colBase + r) * DD + k0 + sg * 8);
        }
    };

    load_chunk(0, 0);
    cpcommit();

    for (int ch = 0; ch < 12; ++ch) {
        cpwait<0>();
        __syncthreads();
        if (ch < 11) { load_chunk(ch + 1, (ch + 1) & 1); cpcommit(); }

        const uint32_t uAh = base + (ch & 1) * OBUF;
        const uint32_t uBh = uAh + GARR;

        #pragma unroll
        for (int kt = 0; kt < 4; ++kt) {
            const uint32_t ko = (uint32_t)kt * 32u;
            uint32_t afh[2][4];
            #pragma unroll
            for (int mi = 0; mi < 2; ++mi)
                ldmat4(afh[mi], uAh + (uint32_t)((wm + mi * 16) * SA) + ko + laneA);
            uint32_t bh[2][4];
            #pragma unroll
            for (int np = 0; np < 2; ++np)
                ldmat4(bh[np], uBh + (uint32_t)((wn + np * 16) * SA) + ko + laneB);

            #pragma unroll
            for (int ni = 0; ni < 4; ++ni) {
                uint32_t b0 = bh[ni >> 1][(ni & 1) * 2];
                uint32_t b1 = bh[ni >> 1][(ni & 1) * 2 + 1];
                #pragma unroll
                for (int mi = 0; mi < 2; ++mi)
                    mma16816h(acc[mi][ni], afh[mi], b0, b1);
            }
        }
    }

    #pragma unroll
    for (int mi = 0; mi < 2; ++mi) {
        int r0 = rowBase + wm + mi * 16 + g;
        int r1 = r0 + 8;
        #pragma unroll
        for (int ni = 0; ni < 4; ++ni) {
            int col = colBase + wn + ni * 8 + 2 * t;
            *(float2*)(outp + (size_t)r0 * DD + col) =
                make_float2(acc[mi][ni][0], acc[mi][ni][1]);
            *(float2*)(outp + (size_t)r1 * DD + col) =
                make_float2(acc[mi][ni][2], acc[mi][ni][3]);
        }
    }
}

// ---------------------------------------------------------------------------
// Flash attention (unchanged from R13): 128 thr, 64 q/CTA, 64-key tiles.
// S single fp16 pass; lazy rescale; P via ex2.approx.f16x2; l via ones-MMA;
// epilogue -> single fp16 ctx.  smem 46080B -> 4 CTAs/SM.
// ---------------------------------------------------------------------------
#define FBUF 18432
#define FQ   9216

__global__ __launch_bounds__(128, 4)
void flash_tc()
{
    extern __shared__ char fsm[];
    const uint32_t base = smem_u32(fsm);
    const uint32_t uQ = base;

    const int tid  = threadIdx.x;
    const int warp = tid >> 5;
    const int lane = tid & 31;
    const int g    = lane >> 2;
    const int t    = lane & 3;
    const int b    = blockIdx.z;
    const int h    = blockIdx.y;
    const int qb   = (gridDim.x - 1) - blockIdx.x;

    const size_t headOff = (size_t)(b * HH + h) * SS * DKK;

    const uint32_t laneA = (uint32_t)(((lane & 7) + ((lane >> 3) & 1) * 8) * SA
                                      + (lane >> 4) * 16);
    const uint32_t laneB = (uint32_t)(((lane & 7) + ((lane >> 4) & 1) * 8) * SA
                                      + ((lane >> 3) & 1) * 16);

    auto load_kv = [&](int kt_tile, int p) {
        uint32_t sb = base + FQ + p * FBUF;
        #pragma unroll
        for (int it = 0; it < 4; ++it) {
            int idx = tid + it * 128;
            int r   = idx >> 3;
            int sg  = idx & 7;
            size_t  s = headOff + (size_t)(kt_tile * 64 + r) * DKK + sg * 8;
            uint32_t d = (uint32_t)(r * SA + sg * 16);
            cp16(sb +         d, g_kh + s);
            cp16(sb + 9216u + d, g_vh + s);
        }
    };

    #pragma unroll
    for (int it = 0; it < 4; ++it) {
        int idx = tid + it * 128;
        int r   = idx >> 3;
        int sg  = idx & 7;
        cp16(uQ + (uint32_t)(r * SA + sg * 16),
             g_qh + headOff + (size_t)(qb * 64 + r) * DKK + sg * 8);
    }
    load_kv(0, 0);
    cpcommit();

    float accO[8][4];
    #pragma unroll
    for (int d = 0; d < 8; ++d)
        #pragma unroll
        for (int r = 0; r < 4; ++r) accO[d][r] = 0.f;
    float lacc[4] = {0.f, 0.f, 0.f, 0.f};
    float m0 = -1e30f, m1 = -1e30f;

    const int qrow = warp * 16 + g;
    const int ntl  = qb + 1;

    for (int ch = 0; ch < ntl; ++ch) {
        cpwait<0>();
        __syncthreads();
        if (ch < ntl - 1) { load_kv(ch + 1, (ch + 1) & 1); cpcommit(); }

        const uint32_t uK = base + FQ + (ch & 1) * FBUF;
        const uint32_t uV = uK + 9216u;

        float sacc[8][4];
        #pragma unroll
        for (int nt = 0; nt < 8; ++nt)
            #pragma unroll
            for (int r = 0; r < 4; ++r) sacc[nt][r] = 0.f;

        #pragma unroll
        for (int kt = 0; kt < 4; ++kt) {
            const uint32_t ko = (uint32_t)kt * 32u;
            uint32_t qa[4];
            ldmat4(qa, uQ + (uint32_t)(warp * 16 * SA) + ko + laneA);
            uint32_t kf[4][4];
            #pragma unroll
            for (int np = 0; np < 4; ++np)
                ldmat4(kf[np], uK + (uint32_t)(np * 16 * SA) + ko + laneB);
            #pragma unroll
            for (int nt = 0; nt < 8; ++nt)
                mma16816h(sacc[nt], qa,
                          kf[nt >> 1][(nt & 1) * 2],
                          kf[nt >> 1][(nt & 1) * 2 + 1]);
        }

        if (ch == qb) {
            #pragma unroll
            for (int nt = 0; nt < 8; ++nt) {
                int kc = nt * 8 + 2 * t;
                if (kc     > qrow)     sacc[nt][0] = -1e30f;
                if (kc + 1 > qrow)     sacc[nt][1] = -1e30f;
                if (kc     > qrow + 8) sacc[nt][2] = -1e30f;
                if (kc + 1 > qrow + 8) sacc[nt][3] = -1e30f;
            }
        }

        float mx0 = -1e30f, mx1 = -1e30f;
        #pragma unroll
        for (int nt = 0; nt < 8; ++nt) {
            mx0 = fmaxf(mx0, fmaxf(sacc[nt][0], sacc[nt][1]));
            mx1 = fmaxf(mx1, fmaxf(sacc[nt][2], sacc[nt][3]));
        }
        mx0 = fmaxf(mx0, __shfl_xor_sync(0xffffffff, mx0, 1));
        mx0 = fmaxf(mx0, __shfl_xor_sync(0xffffffff, mx0, 2));
        mx1 = fmaxf(mx1, __shfl_xor_sync(0xffffffff, mx1, 1));
        mx1 = fmaxf(mx1, __shfl_xor_sync(0xffffffff, mx1, 2));

        bool upd = (mx0 > m0) || (mx1 > m1);
        if (__any_sync(0xffffffff, upd)) {
            float mn0 = fmaxf(m0, mx0), mn1 = fmaxf(m1, mx1);
            float cr0 = ex2f(m0 - mn0), cr1 = ex2f(m1 - mn1);
            m0 = mn0; m1 = mn1;
            lacc[0] *= cr0; lacc[1] *= cr0;
            lacc[2] *= cr1; lacc[3] *= cr1;
            #pragma unroll
            for (int d = 0; d < 8; ++d) {
                accO[d][0] *= cr0; accO[d][1] *= cr0;
                accO[d][2] *= cr1; accO[d][3] *= cr1;
            }
        }

        uint32_t pah[4][4];
        #pragma unroll
        for (int nt = 0; nt < 8; ++nt) {
            uint32_t u01 = ex2h2(pkhf(sacc[nt][0] - m0, sacc[nt][1] - m0));
            uint32_t u23 = ex2h2(pkhf(sacc[nt][2] - m1, sacc[nt][3] - m1));
            int kt = nt >> 1;
            if ((nt & 1) == 0) { pah[kt][0] = u01; pah[kt][1] = u23; }
            else               { pah[kt][2] = u01; pah[kt][3] = u23; }
        }

        #pragma unroll
        for (int kt = 0; kt < 4; ++kt)
            mma16816h(lacc, pah[kt], ONES2, ONES2);

        const int mat = lane >> 3;
        const int rr  = lane & 7;
        #pragma unroll
        for (int kt = 0; kt < 4; ++kt) {
            #pragma unroll
            for (int pr = 0; pr < 4; ++pr) {
                uint32_t off = (uint32_t)((kt * 16 + rr + (mat & 1) * 8) * SA)
                             + (uint32_t)((pr * 16 + (mat >> 1) * 8) * 2);
                uint32_t vv[4];
                ldmat4t(vv, uV + off);
                mma16816h(accO[2 * pr],     pah[kt], vv[0], vv[1]);
                mma16816h(accO[2 * pr + 1], pah[kt], vv[2], vv[3]);
            }
        }
    }

    float inv0 = 1.0f / lacc[0], inv1 = 1.0f / lacc[2];

    int q0 = qb * 64 + qrow;
    size_t base0 = ((size_t)b * SS + q0) * DD + h * DKK;
    size_t base1 = base0 + (size_t)8 * DD;
    #pragma unroll
    for (int d = 0; d < 8; ++d) {
        int col = d * 8 + 2 * t;
        *(uint32_t*)(g_ch + base0 + col) =
            pkhf(accO[d][0] * inv0, accO[d][1] * inv0);
        *(uint32_t*)(g_ch + base1 + col) =
            pkhf(accO[d][2] * inv1, accO[d][3] * inv1);
    }
}

// ---------------------------------------------------------------------------
extern "C" void kernel_launch(void* const* d_in, const int* in_sizes, int n_in,
                              void* d_out, int out_size)
{
    (void)in_sizes; (void)n_in; (void)out_size;
    const float* Q  = (const float*)d_in[0];
    const float* K  = (const float*)d_in[1];
    const float* V  = (const float*)d_in[2];
    const float* Wq = (const float*)d_in[4];
    const float* Wk = (const float*)d_in[5];
    const float* Wv = (const float*)d_in[6];
    const float* Wo = (const float*)d_in[7];
    float* out = (float*)d_out;

    constexpr int PROJ_SMEM  = 2 * GBUF;      // 73728
    constexpr int OUT_SMEM   = 2 * OBUF;      // 55296
    constexpr int FLASH_SMEM = FQ + 2 * FBUF; // 46080
    static bool attr_done = false;
    if (!attr_done) {
        cudaFuncSetAttribute(gemm_proj,
                             cudaFuncAttributeMaxDynamicSharedMemorySize, PROJ_SMEM);
        cudaFuncSetAttribute(gemm_out,
                             cudaFuncAttributeMaxDynamicSharedMemorySize, OUT_SMEM);
        cudaFuncSetAttribute(flash_tc,
                             cudaFuncAttributeMaxDynamicSharedMemorySize, FLASH_SMEM);
        attr_done = true;
    }

    // fused conversion: (3*XN + 4*WN)/4/256 = 11520 blocks
    conv_all<<<11520, 256>>>(Q, K, V, Wq, Wk, Wv, Wo);

    gemm_proj<<<dim3(DD / 128, (BB * SS) / 128, 3), 256, PROJ_SMEM>>>();

    flash_tc<<<dim3(SS / 64, HH, BB), 128, FLASH_SMEM>>>();

    gemm_out<<<dim3(DD / 64, (BB * SS) / 128, 1), 256, OUT_SMEM>>>(out);
}